// round 7
// baseline (speedup 1.0000x reference)
#include <cuda_runtime.h>
#include <cuda_bf16.h>
#include <math.h>
#include <stdint.h>

// ---------------------------------------------------------------------------
// Problem constants
// ---------------------------------------------------------------------------
#define EMBED  768
#define NWIN   200
#define NTOK   196
#define NHEAD  12
#define HD     64
#define M_TOK  32768
#define FFDIM  3072
#define QKVN   2304

// ---------------------------------------------------------------------------
// Scratch (device globals; no allocation allowed)
// ---------------------------------------------------------------------------
__device__ __nv_bfloat16 g_hwin_hi[(size_t)M_TOK*EMBED];
__device__ __nv_bfloat16 g_hwin_lo[(size_t)M_TOK*EMBED];
__device__ float         g_qkv   [(size_t)M_TOK*QKVN];
__device__ __nv_bfloat16 g_attn_hi[(size_t)M_TOK*EMBED];
__device__ __nv_bfloat16 g_attn_lo[(size_t)M_TOK*EMBED];
__device__ float         g_x1    [(size_t)M_TOK*EMBED];
__device__ __nv_bfloat16 g_h2_hi [(size_t)M_TOK*EMBED];
__device__ __nv_bfloat16 g_h2_lo [(size_t)M_TOK*EMBED];
__device__ __nv_bfloat16 g_ff_hi [(size_t)M_TOK*FFDIM];
__device__ __nv_bfloat16 g_ff_lo [(size_t)M_TOK*FFDIM];
// transposed split weights: [N][K]
__device__ __nv_bfloat16 g_wqkv_hi[(size_t)QKVN*EMBED];
__device__ __nv_bfloat16 g_wqkv_lo[(size_t)QKVN*EMBED];
__device__ __nv_bfloat16 g_wprj_hi[(size_t)EMBED*EMBED];
__device__ __nv_bfloat16 g_wprj_lo[(size_t)EMBED*EMBED];
__device__ __nv_bfloat16 g_wfc1_hi[(size_t)FFDIM*EMBED];
__device__ __nv_bfloat16 g_wfc1_lo[(size_t)FFDIM*EMBED];
__device__ __nv_bfloat16 g_wfc2_hi[(size_t)EMBED*FFDIM];
__device__ __nv_bfloat16 g_wfc2_lo[(size_t)EMBED*FFDIM];

// ---------------------------------------------------------------------------
// Helpers
// ---------------------------------------------------------------------------
__device__ __forceinline__ float gelu_f(float v) {
    return 0.5f * v * (1.0f + erff(v * 0.7071067811865476f));
}
__device__ __forceinline__ void split2(float v, __nv_bfloat16& h, __nv_bfloat16& l) {
    h = __float2bfloat16(v);
    l = __float2bfloat16(v - __bfloat162float(h));
}
__device__ __forceinline__ uint32_t s2u(const void* p) {
    uint32_t a;
    asm("{ .reg .u64 t; cvta.to.shared.u64 t, %1; cvt.u32.u64 %0, t; }" : "=r"(a) : "l"(p));
    return a;
}
__device__ __forceinline__ void ldsm_x4(uint32_t& r0, uint32_t& r1, uint32_t& r2,
                                        uint32_t& r3, uint32_t addr) {
    asm volatile("ldmatrix.sync.aligned.m8n8.x4.shared.b16 {%0,%1,%2,%3}, [%4];"
                 : "=r"(r0), "=r"(r1), "=r"(r2), "=r"(r3) : "r"(addr));
}
__device__ __forceinline__ void mma16816(float* c, const uint32_t* a,
                                         uint32_t b0, uint32_t b1) {
    asm volatile(
        "mma.sync.aligned.m16n8k16.row.col.f32.bf16.bf16.f32 "
        "{%0,%1,%2,%3}, {%4,%5,%6,%7}, {%8,%9}, {%0,%1,%2,%3};"
        : "+f"(c[0]), "+f"(c[1]), "+f"(c[2]), "+f"(c[3])
        : "r"(a[0]), "r"(a[1]), "r"(a[2]), "r"(a[3]), "r"(b0), "r"(b1));
}
__device__ __forceinline__ void cp16(uint32_t saddr, const void* g) {
    asm volatile("cp.async.cg.shared.global [%0], [%1], 16;" :: "r"(saddr), "l"(g));
}
__device__ __forceinline__ void cp_commit() {
    asm volatile("cp.async.commit_group;");
}

// ---------------------------------------------------------------------------
// Weight prep: transpose [K,N] fp32 -> [N,K] bf16 hi/lo
// ---------------------------------------------------------------------------
__global__ __launch_bounds__(256) void wprep(
    const float* __restrict__ W, __nv_bfloat16* __restrict__ Th,
    __nv_bfloat16* __restrict__ Tl, int K, int N)
{
    __shared__ float t[32][33];
    const int n0 = blockIdx.x * 32, k0 = blockIdx.y * 32;
    const int tx = threadIdx.x & 31, ty = threadIdx.x >> 5;
    #pragma unroll
    for (int i = 0; i < 32; i += 8)
        t[ty + i][tx] = W[(size_t)(k0 + ty + i) * N + n0 + tx];
    __syncthreads();
    #pragma unroll
    for (int i = 0; i < 32; i += 8) {
        float v = t[tx][ty + i];
        __nv_bfloat16 h, l; split2(v, h, l);
        size_t o = (size_t)(n0 + ty + i) * K + k0 + tx;
        Th[o] = h; Tl[o] = l;
    }
}

// ---------------------------------------------------------------------------
// LayerNorm over contiguous rows -> split bf16 (used for LN1 and LN2)
// ---------------------------------------------------------------------------
__global__ __launch_bounds__(256) void ln_kernel(
    const float* __restrict__ xin, const float* __restrict__ g,
    const float* __restrict__ b, __nv_bfloat16* __restrict__ ohi,
    __nv_bfloat16* __restrict__ olo)
{
    __shared__ float red[16];
    const int row = blockIdx.x, tid = threadIdx.x;
    const float* xr = xin + (size_t)row * EMBED;
    const size_t ro = (size_t)row * EMBED;
    float v0 = xr[tid], v1 = xr[tid+256], v2 = xr[tid+512];
    float s = v0+v1+v2, s2 = v0*v0+v1*v1+v2*v2;
    #pragma unroll
    for (int o = 16; o; o >>= 1) {
        s  += __shfl_xor_sync(0xffffffffu, s,  o);
        s2 += __shfl_xor_sync(0xffffffffu, s2, o);
    }
    if ((tid & 31) == 0) { red[tid>>5] = s; red[8+(tid>>5)] = s2; }
    __syncthreads();
    float S=0.f, S2=0.f;
    #pragma unroll
    for (int i = 0; i < 8; i++) { S += red[i]; S2 += red[8+i]; }
    const float mean = S * (1.f/768.f);
    const float rstd = rsqrtf(S2*(1.f/768.f) - mean*mean + 1e-6f);
    __nv_bfloat16 h, l;
    float o0 = (v0-mean)*rstd*g[tid]     + b[tid];
    float o1 = (v1-mean)*rstd*g[tid+256] + b[tid+256];
    float o2 = (v2-mean)*rstd*g[tid+512] + b[tid+512];
    split2(o0,h,l); ohi[ro+tid]=h;     olo[ro+tid]=l;
    split2(o1,h,l); ohi[ro+tid+256]=h; olo[ro+tid+256]=l;
    split2(o2,h,l); ohi[ro+tid+512]=h; olo[ro+tid+512]=l;
}

// ---------------------------------------------------------------------------
// HMMA GEMM: C[M,N] = A[M,K] @ B[N,K]^T (+bias), 3-term bf16 split.
// CTA 256x128, 8 warps of 64x64 (4M x 2N), K-chunk 32, double-buffered.
// M must be a multiple of 256, N of 128, K of 32.
// EPI: 0 bias->fp32 | 1 bias+gelu->bf16 splits | 2 bias+res->fp32
// ---------------------------------------------------------------------------
#define LDA        40                      // bf16 per smem row
#define A_BYTES    (256*LDA*2)             // 20480
#define B_BYTES    (128*LDA*2)             // 10240
#define BUF_BYTES  (2*A_BYTES + 2*B_BYTES) // 61440
#define GSM_BYTES  (2*BUF_BYTES)           // 122880

template<int EPI>
__global__ __launch_bounds__(256, 1) void tgemm(
    const __nv_bfloat16* __restrict__ Ah, const __nv_bfloat16* __restrict__ Al,
    const __nv_bfloat16* __restrict__ Bh, const __nv_bfloat16* __restrict__ Bl,
    const float* __restrict__ bias, float* __restrict__ Co,
    __nv_bfloat16* __restrict__ Chi, __nv_bfloat16* __restrict__ Clo,
    int M, int N, int K, const float* __restrict__ res)
{
    extern __shared__ char smc[];
    const uint32_t smb = s2u(smc);
    const int tid = threadIdx.x;
    const int wid = tid >> 5, lane = tid & 31;
    const int bm = blockIdx.y * 256, bn = blockIdx.x * 128;
    const int wm = wid & 3, wn = wid >> 2;      // warp tile: 64 (M) x 64 (N)
    const int NC = K >> 5;

    float acc[4][8][4];
    #pragma unroll
    for (int i = 0; i < 4; i++)
        #pragma unroll
        for (int j = 0; j < 8; j++)
            #pragma unroll
            for (int k = 0; k < 4; k++) acc[i][j][k] = 0.f;

    const uint32_t offA = (uint32_t)((wm*64 + (lane & 7) + 8*((lane >> 3) & 1)) * LDA
                                     + 8*(lane >> 4)) * 2;
    const uint32_t offB = (uint32_t)((wn*64 + (lane & 7) + 8*(lane >> 4)) * LDA
                                     + 8*((lane >> 3) & 1)) * 2;

    auto load_chunk = [&](int c, int b) {
        const int k0 = c << 5;
        const uint32_t bb = smb + b * BUF_BYTES;
        #pragma unroll
        for (int a = 0; a < 2; a++) {              // A hi/lo: 256 rows
            const __nv_bfloat16* G = a ? Al : Ah;
            const uint32_t ab = bb + a * A_BYTES;
            #pragma unroll
            for (int s = 0; s < 4; s++) {
                const int u = tid + s * 256;        // [0,1024)
                const int row = u >> 2, seg = u & 3;
                cp16(ab + (uint32_t)(row * LDA + seg * 8) * 2,
                     G + (size_t)(bm + row) * K + k0 + seg * 8);
            }
        }
        #pragma unroll
        for (int a = 0; a < 2; a++) {              // B hi/lo: 128 rows
            const __nv_bfloat16* G = a ? Bl : Bh;
            const uint32_t ab = bb + 2*A_BYTES + a * B_BYTES;
            #pragma unroll
            for (int s = 0; s < 2; s++) {
                const int u = tid + s * 256;        // [0,512)
                const int row = u >> 2, seg = u & 3;
                cp16(ab + (uint32_t)(row * LDA + seg * 8) * 2,
                     G + (size_t)(bn + row) * K + k0 + seg * 8);
            }
        }
        cp_commit();
    };

    load_chunk(0, 0);

    for (int c = 0; c < NC; c++) {
        const int b = c & 1;
        if (c + 1 < NC) {
            load_chunk(c + 1, b ^ 1);
            asm volatile("cp.async.wait_group 1;");
        } else {
            asm volatile("cp.async.wait_group 0;");
        }
        __syncthreads();

        const uint32_t bb  = smb + b * BUF_BYTES;
        const uint32_t pAh = bb + offA;
        const uint32_t pAl = bb + A_BYTES + offA;
        const uint32_t pBh = bb + 2*A_BYTES + offB;
        const uint32_t pBl = bb + 2*A_BYTES + B_BYTES + offB;

        #pragma unroll
        for (int ks = 0; ks < 2; ks++) {
            const uint32_t kso = ks * 32;           // 16 bf16 = 32 bytes
            uint32_t ah[4][4], bh[8][2], bl[8][2];
            #pragma unroll
            for (int mt = 0; mt < 4; mt++)
                ldsm_x4(ah[mt][0], ah[mt][1], ah[mt][2], ah[mt][3],
                        pAh + kso + mt * (16*LDA*2));
            #pragma unroll
            for (int L = 0; L < 4; L++) {
                ldsm_x4(bh[2*L][0], bh[2*L][1], bh[2*L+1][0], bh[2*L+1][1],
                        pBh + kso + L * (16*LDA*2));
                ldsm_x4(bl[2*L][0], bl[2*L][1], bl[2*L+1][0], bl[2*L+1][1],
                        pBl + kso + L * (16*LDA*2));
            }
            #pragma unroll
            for (int mt = 0; mt < 4; mt++)
                #pragma unroll
                for (int nt = 0; nt < 8; nt++)
                    mma16816(acc[mt][nt], ah[mt], bh[nt][0], bh[nt][1]);
            #pragma unroll
            for (int mt = 0; mt < 4; mt++)
                #pragma unroll
                for (int nt = 0; nt < 8; nt++)
                    mma16816(acc[mt][nt], ah[mt], bl[nt][0], bl[nt][1]);
            #pragma unroll
            for (int mt = 0; mt < 4; mt++)
                ldsm_x4(ah[mt][0], ah[mt][1], ah[mt][2], ah[mt][3],
                        pAl + kso + mt * (16*LDA*2));
            #pragma unroll
            for (int mt = 0; mt < 4; mt++)
                #pragma unroll
                for (int nt = 0; nt < 8; nt++)
                    mma16816(acc[mt][nt], ah[mt], bh[nt][0], bh[nt][1]);
        }
        __syncthreads();
    }

    // -------- epilogue --------
    const int rbase = bm + wm*64;
    const int nbase = bn + wn*64;
    #pragma unroll
    for (int mt = 0; mt < 4; mt++) {
        #pragma unroll
        for (int half = 0; half < 2; half++) {
            const int m = rbase + mt*16 + (lane >> 2) + half*8;
            #pragma unroll
            for (int nt = 0; nt < 8; nt++) {
                const int n = nbase + nt*8 + (lane & 3)*2;
                float v0 = acc[mt][nt][half*2 + 0] + bias[n];
                float v1 = acc[mt][nt][half*2 + 1] + bias[n + 1];
                if (EPI == 0) {
                    *(float2*)(Co + (size_t)m * N + n) = make_float2(v0, v1);
                } else if (EPI == 1) {
                    v0 = gelu_f(v0); v1 = gelu_f(v1);
                    __nv_bfloat162 H, L;
                    split2(v0, H.x, L.x); split2(v1, H.y, L.y);
                    *(__nv_bfloat162*)(Chi + (size_t)m * N + n) = H;
                    *(__nv_bfloat162*)(Clo + (size_t)m * N + n) = L;
                } else {
                    const float2 r2 = *(const float2*)(res + (size_t)m * N + n);
                    *(float2*)(Co + (size_t)m * N + n) = make_float2(v0 + r2.x, v1 + r2.y);
                }
            }
        }
    }
}

// ---------------------------------------------------------------------------
// Window attention. QKV is COMPACT (M_TOK rows, x-layout); this kernel does
// the window gather (padded tokens use b_qkv bias, matching zero-padded LN
// rows through the projection) and scatters output back to compact layout.
// ---------------------------------------------------------------------------
#define ATTN_SMEM_FLOATS (NTOK*68 + NTOK*68 + NTOK*64 + 27*64 + 27*64 + NTOK*14 + NTOK*14 + 8*2*NTOK)
#define ATTN_SMEM_BYTES  (ATTN_SMEM_FLOATS * 4)

__global__ __launch_bounds__(256) void attn_kernel(
    const float* __restrict__ qkv, const float* __restrict__ bqkv,
    const float* __restrict__ relh, const float* __restrict__ relw,
    __nv_bfloat16* __restrict__ aohi, __nv_bfloat16* __restrict__ aolo)
{
    extern __shared__ float sm[];
    float* Qs  = sm;
    float* Ks  = Qs  + NTOK * 68;
    float* Vs  = Ks  + NTOK * 68;
    float* Rh  = Vs  + NTOK * 64;
    float* Rw  = Rh  + 27 * 64;
    float* BHs = Rw  + 27 * 64;
    float* BWs = BHs + NTOK * 14;
    float* Ps  = BWs + NTOK * 14;

    const int tid = threadIdx.x;
    const int w = blockIdx.x / NHEAD, h = blockIdx.x % NHEAD;
    const int bI = w / 25, wr = w % 25;
    const int wy = wr / 5, wx = wr % 5;

    for (int idx = tid; idx < NTOK * 16; idx += 256) {
        const int t = idx >> 4, c4 = (idx & 15) << 2;
        const int y = wy * 14 + t / 14, xx = wx * 14 + t % 14;
        const float* rp = (y < 64 && xx < 64)
            ? qkv + (size_t)((bI * 64 + y) * 64 + xx) * QKVN + h * HD
            : bqkv + h * HD;
        float4 q4 = *(const float4*)(rp + c4);
        float4 k4 = *(const float4*)(rp + 768 + c4);
        float4 v4 = *(const float4*)(rp + 1536 + c4);
        *(float4*)&Qs[t * 68 + c4] = q4;
        *(float4*)&Ks[t * 68 + c4] = k4;
        *(float4*)&Vs[t * 64 + c4] = v4;
    }
    for (int idx = tid; idx < 27 * 64; idx += 256) { Rh[idx] = relh[idx]; Rw[idx] = relw[idx]; }
    __syncthreads();

    const int wid = tid >> 5, lane = tid & 31;

    for (int i = wid; i < NTOK; i += 8) {
        const int p = i / 14, qc = i % 14;
        const float2 q2 = *(const float2*)&Qs[i * 68 + 2 * lane];
        float acch[14], accw[14];
        #pragma unroll
        for (int r = 0; r < 14; r++) {
            const float2 rh2 = *(const float2*)&Rh[(p  + 13 - r) * 64 + 2 * lane];
            const float2 rw2 = *(const float2*)&Rw[(qc + 13 - r) * 64 + 2 * lane];
            acch[r] = q2.x * rh2.x + q2.y * rh2.y;
            accw[r] = q2.x * rw2.x + q2.y * rw2.y;
        }
        #pragma unroll
        for (int o = 16; o; o >>= 1) {
            #pragma unroll
            for (int r = 0; r < 14; r++) {
                acch[r] += __shfl_xor_sync(0xffffffffu, acch[r], o);
                accw[r] += __shfl_xor_sync(0xffffffffu, accw[r], o);
            }
        }
        if (lane == 0) {
            #pragma unroll
            for (int r = 0; r < 14; r++) { BHs[i*14+r] = acch[r]; BWs[i*14+r] = accw[r]; }
        }
    }
    __syncthreads();

    const float SCALE = 0.125f;
    float* P0 = Ps + wid * (2 * NTOK);
    float* P1 = P0 + NTOK;

    for (int i0 = wid * 2; i0 < NTOK; i0 += 16) {
        const int i1 = i0 + 1;
        const float* q0p = &Qs[i0 * 68];
        const float* q1p = &Qs[i1 * 68];
        float s0[7], s1[7];
        float mx0 = -1e30f, mx1 = -1e30f;
        #pragma unroll
        for (int jj = 0; jj < 7; jj++) {
            const int j = jj * 32 + lane;
            float a0 = -1e30f, a1 = -1e30f;
            if (j < NTOK) {
                const float* kr = &Ks[j * 68];
                float d0 = 0.f, d1 = 0.f;
                #pragma unroll
                for (int d = 0; d < 64; d += 4) {
                    float4 k4 = *(const float4*)(kr + d);
                    float4 qa = *(const float4*)(q0p + d);
                    float4 qb = *(const float4*)(q1p + d);
                    d0 += qa.x*k4.x + qa.y*k4.y + qa.z*k4.z + qa.w*k4.w;
                    d1 += qb.x*k4.x + qb.y*k4.y + qb.z*k4.z + qb.w*k4.w;
                }
                const int jp = j / 14, jq = j % 14;
                a0 = d0 * SCALE + BHs[i0*14+jp] + BWs[i0*14+jq];
                a1 = d1 * SCALE + BHs[i1*14+jp] + BWs[i1*14+jq];
            }
            s0[jj] = a0; s1[jj] = a1;
            mx0 = fmaxf(mx0, a0); mx1 = fmaxf(mx1, a1);
        }
        #pragma unroll
        for (int o = 16; o; o >>= 1) {
            mx0 = fmaxf(mx0, __shfl_xor_sync(0xffffffffu, mx0, o));
            mx1 = fmaxf(mx1, __shfl_xor_sync(0xffffffffu, mx1, o));
        }
        float sum0 = 0.f, sum1 = 0.f;
        #pragma unroll
        for (int jj = 0; jj < 7; jj++) {
            float e0 = __expf(s0[jj] - mx0);
            float e1 = __expf(s1[jj] - mx1);
            if (jj * 32 + lane >= NTOK) { e0 = 0.f; e1 = 0.f; }
            s0[jj] = e0; s1[jj] = e1;
            sum0 += e0; sum1 += e1;
        }
        #pragma unroll
        for (int o = 16; o; o >>= 1) {
            sum0 += __shfl_xor_sync(0xffffffffu, sum0, o);
            sum1 += __shfl_xor_sync(0xffffffffu, sum1, o);
        }
        const float r0 = 1.f / sum0, r1 = 1.f / sum1;
        #pragma unroll
        for (int jj = 0; jj < 7; jj++) {
            const int j = jj * 32 + lane;
            if (j < NTOK) { P0[j] = s0[jj] * r0; P1[j] = s1[jj] * r1; }
        }
        __syncwarp();
        float o00 = 0.f, o01 = 0.f, o10 = 0.f, o11 = 0.f;
        #pragma unroll 7
        for (int j4 = 0; j4 < 49; j4++) {
            const float4 p0 = *(const float4*)(P0 + j4 * 4);
            const float4 p1 = *(const float4*)(P1 + j4 * 4);
            const float* vb = &Vs[j4 * 4 * 64 + 2 * lane];
            const float2 v0 = *(const float2*)(vb);
            const float2 v1 = *(const float2*)(vb + 64);
            const float2 v2 = *(const float2*)(vb + 128);
            const float2 v3 = *(const float2*)(vb + 192);
            o00 += p0.x*v0.x + p0.y*v1.x + p0.z*v2.x + p0.w*v3.x;
            o01 += p0.x*v0.y + p0.y*v1.y + p0.z*v2.y + p0.w*v3.y;
            o10 += p1.x*v0.x + p1.y*v1.x + p1.z*v2.x + p1.w*v3.x;
            o11 += p1.x*v0.y + p1.y*v1.y + p1.z*v2.y + p1.w*v3.y;
        }
        // scatter to compact layout, skipping padded tokens
        const int y0 = wy*14 + i0/14, x0 = wx*14 + i0%14;
        const int y1 = wy*14 + i1/14, x1p = wx*14 + i1%14;
        __nv_bfloat162 Hh, Ll;
        if (y0 < 64 && x0 < 64) {
            const size_t ro = (size_t)((bI*64 + y0)*64 + x0) * EMBED + h * HD + 2*lane;
            split2(o00, Hh.x, Ll.x); split2(o01, Hh.y, Ll.y);
            *(__nv_bfloat162*)(aohi + ro) = Hh; *(__nv_bfloat162*)(aolo + ro) = Ll;
        }
        if (y1 < 64 && x1p < 64) {
            const size_t ro = (size_t)((bI*64 + y1)*64 + x1p) * EMBED + h * HD + 2*lane;
            split2(o10, Hh.x, Ll.x); split2(o11, Hh.y, Ll.y);
            *(__nv_bfloat162*)(aohi + ro) = Hh; *(__nv_bfloat162*)(aolo + ro) = Ll;
        }
        __syncwarp();
    }
}

// ---------------------------------------------------------------------------
// kernel_launch
// ---------------------------------------------------------------------------
extern "C" void kernel_launch(void* const* d_in, const int* in_sizes, int n_in,
                              void* d_out, int out_size)
{
    const float* x      = (const float*)d_in[0];
    const float* g1     = (const float*)d_in[1];
    const float* beta1  = (const float*)d_in[2];
    const float* w_qkv  = (const float*)d_in[3];
    const float* b_qkv  = (const float*)d_in[4];
    const float* w_proj = (const float*)d_in[5];
    const float* b_proj = (const float*)d_in[6];
    const float* relh   = (const float*)d_in[7];
    const float* relw   = (const float*)d_in[8];
    const float* g2     = (const float*)d_in[9];
    const float* beta2  = (const float*)d_in[10];
    const float* w_fc1  = (const float*)d_in[11];
    const float* b_fc1  = (const float*)d_in[12];
    const float* w_fc2  = (const float*)d_in[13];
    const float* b_fc2  = (const float*)d_in[14];
    float* out = (float*)d_out;

    __nv_bfloat16 *hwin_h, *hwin_l, *attn_h, *attn_l, *h2_h, *h2_l, *ff_h, *ff_l;
    __nv_bfloat16 *wqkv_h, *wqkv_l, *wprj_h, *wprj_l, *wf1_h, *wf1_l, *wf2_h, *wf2_l;
    float *qkv, *x1;
    cudaGetSymbolAddress((void**)&hwin_h, g_hwin_hi);
    cudaGetSymbolAddress((void**)&hwin_l, g_hwin_lo);
    cudaGetSymbolAddress((void**)&qkv,    g_qkv);
    cudaGetSymbolAddress((void**)&attn_h, g_attn_hi);
    cudaGetSymbolAddress((void**)&attn_l, g_attn_lo);
    cudaGetSymbolAddress((void**)&x1,     g_x1);
    cudaGetSymbolAddress((void**)&h2_h,   g_h2_hi);
    cudaGetSymbolAddress((void**)&h2_l,   g_h2_lo);
    cudaGetSymbolAddress((void**)&ff_h,   g_ff_hi);
    cudaGetSymbolAddress((void**)&ff_l,   g_ff_lo);
    cudaGetSymbolAddress((void**)&wqkv_h, g_wqkv_hi);
    cudaGetSymbolAddress((void**)&wqkv_l, g_wqkv_lo);
    cudaGetSymbolAddress((void**)&wprj_h, g_wprj_hi);
    cudaGetSymbolAddress((void**)&wprj_l, g_wprj_lo);
    cudaGetSymbolAddress((void**)&wf1_h,  g_wfc1_hi);
    cudaGetSymbolAddress((void**)&wf1_l,  g_wfc1_lo);
    cudaGetSymbolAddress((void**)&wf2_h,  g_wfc2_hi);
    cudaGetSymbolAddress((void**)&wf2_l,  g_wfc2_lo);

    cudaFuncSetAttribute(attn_kernel, cudaFuncAttributeMaxDynamicSharedMemorySize, ATTN_SMEM_BYTES);
    cudaFuncSetAttribute(tgemm<0>, cudaFuncAttributeMaxDynamicSharedMemorySize, GSM_BYTES);
    cudaFuncSetAttribute(tgemm<1>, cudaFuncAttributeMaxDynamicSharedMemorySize, GSM_BYTES);
    cudaFuncSetAttribute(tgemm<2>, cudaFuncAttributeMaxDynamicSharedMemorySize, GSM_BYTES);

    // weight prep (transpose + bf16 split)
    wprep<<<dim3(QKVN/32, EMBED/32), 256>>>(w_qkv,  wqkv_h, wqkv_l, EMBED, QKVN);
    wprep<<<dim3(EMBED/32, EMBED/32), 256>>>(w_proj, wprj_h, wprj_l, EMBED, EMBED);
    wprep<<<dim3(FFDIM/32, EMBED/32), 256>>>(w_fc1,  wf1_h,  wf1_l,  EMBED, FFDIM);
    wprep<<<dim3(EMBED/32, FFDIM/32), 256>>>(w_fc2,  wf2_h,  wf2_l,  FFDIM, EMBED);

    // 1. LN1 (compact layout)
    ln_kernel<<<M_TOK, 256>>>(x, g1, beta1, hwin_h, hwin_l);

    // 2. QKV projection (compact, M=32768)
    tgemm<0><<<dim3(QKVN/128, M_TOK/256), 256, GSM_BYTES>>>(
        hwin_h, hwin_l, wqkv_h, wqkv_l, b_qkv, qkv, nullptr, nullptr,
        M_TOK, QKVN, EMBED, nullptr);

    // 3. Window attention (gather + scatter inside)
    attn_kernel<<<NWIN * NHEAD, 256, ATTN_SMEM_BYTES>>>(qkv, b_qkv, relh, relw, attn_h, attn_l);

    // 4. proj + residual: x1 = x + attn @ w_proj + b_proj
    tgemm<2><<<dim3(EMBED/128, M_TOK/256), 256, GSM_BYTES>>>(
        attn_h, attn_l, wprj_h, wprj_l, b_proj, x1, nullptr, nullptr,
        M_TOK, EMBED, EMBED, x);

    // 5. LN2
    ln_kernel<<<M_TOK, 256>>>(x1, g2, beta2, h2_h, h2_l);

    // 6. fc1 + GELU -> split bf16
    tgemm<1><<<dim3(FFDIM/128, M_TOK/256), 256, GSM_BYTES>>>(
        h2_h, h2_l, wf1_h, wf1_l, b_fc1, nullptr, ff_h, ff_l,
        M_TOK, FFDIM, EMBED, nullptr);

    // 7. fc2 + residual -> out
    tgemm<2><<<dim3(EMBED/128, M_TOK/256), 256, GSM_BYTES>>>(
        ff_h, ff_l, wf2_h, wf2_l, b_fc2, out, nullptr, nullptr,
        M_TOK, EMBED, FFDIM, x1);
}

// round 8
// speedup vs baseline: 1.7588x; 1.7588x over previous
#include <cuda_runtime.h>
#include <cuda_fp16.h>
#include <math.h>
#include <stdint.h>

// ---------------------------------------------------------------------------
// Problem constants
// ---------------------------------------------------------------------------
#define EMBED  768
#define NWIN   200
#define NTOK   196
#define NHEAD  12
#define HD     64
#define M_TOK  32768
#define FFDIM  3072
#define QKVN   2304

// ---------------------------------------------------------------------------
// Scratch (device globals; no allocation allowed)
// ---------------------------------------------------------------------------
__device__ __half g_hwin[(size_t)M_TOK*EMBED];
__device__ float  g_qkv [(size_t)M_TOK*QKVN];
__device__ __half g_attn[(size_t)M_TOK*EMBED];
__device__ float  g_x1  [(size_t)M_TOK*EMBED];
__device__ __half g_h2  [(size_t)M_TOK*EMBED];
__device__ __half g_ff  [(size_t)M_TOK*FFDIM];
// transposed fp16 weights: [N][K]
__device__ __half g_wqkv[(size_t)QKVN*EMBED];
__device__ __half g_wprj[(size_t)EMBED*EMBED];
__device__ __half g_wfc1[(size_t)FFDIM*EMBED];
__device__ __half g_wfc2[(size_t)EMBED*FFDIM];

// ---------------------------------------------------------------------------
// Helpers
// ---------------------------------------------------------------------------
__device__ __forceinline__ float gelu_f(float v) {
    return 0.5f * v * (1.0f + erff(v * 0.7071067811865476f));
}
__device__ __forceinline__ uint32_t s2u(const void* p) {
    uint32_t a;
    asm("{ .reg .u64 t; cvta.to.shared.u64 t, %1; cvt.u32.u64 %0, t; }" : "=r"(a) : "l"(p));
    return a;
}
__device__ __forceinline__ void ldsm_x4(uint32_t& r0, uint32_t& r1, uint32_t& r2,
                                        uint32_t& r3, uint32_t addr) {
    asm volatile("ldmatrix.sync.aligned.m8n8.x4.shared.b16 {%0,%1,%2,%3}, [%4];"
                 : "=r"(r0), "=r"(r1), "=r"(r2), "=r"(r3) : "r"(addr));
}
__device__ __forceinline__ void mma16816(float* c, const uint32_t* a,
                                         uint32_t b0, uint32_t b1) {
    asm volatile(
        "mma.sync.aligned.m16n8k16.row.col.f32.f16.f16.f32 "
        "{%0,%1,%2,%3}, {%4,%5,%6,%7}, {%8,%9}, {%0,%1,%2,%3};"
        : "+f"(c[0]), "+f"(c[1]), "+f"(c[2]), "+f"(c[3])
        : "r"(a[0]), "r"(a[1]), "r"(a[2]), "r"(a[3]), "r"(b0), "r"(b1));
}
__device__ __forceinline__ void cp16(uint32_t saddr, const void* g) {
    asm volatile("cp.async.cg.shared.global [%0], [%1], 16;" :: "r"(saddr), "l"(g));
}
__device__ __forceinline__ void cp_commit() {
    asm volatile("cp.async.commit_group;");
}

// ---------------------------------------------------------------------------
// Weight prep: transpose [K,N] fp32 -> [N,K] fp16
// ---------------------------------------------------------------------------
__global__ __launch_bounds__(256) void wprep(
    const float* __restrict__ W, __half* __restrict__ T, int K, int N)
{
    __shared__ float t[32][33];
    const int n0 = blockIdx.x * 32, k0 = blockIdx.y * 32;
    const int tx = threadIdx.x & 31, ty = threadIdx.x >> 5;
    #pragma unroll
    for (int i = 0; i < 32; i += 8)
        t[ty + i][tx] = W[(size_t)(k0 + ty + i) * N + n0 + tx];
    __syncthreads();
    #pragma unroll
    for (int i = 0; i < 32; i += 8)
        T[(size_t)(n0 + ty + i) * K + k0 + tx] = __float2half(t[tx][ty + i]);
}

// ---------------------------------------------------------------------------
// LayerNorm over contiguous rows -> fp16
// ---------------------------------------------------------------------------
__global__ __launch_bounds__(256) void ln_kernel(
    const float* __restrict__ xin, const float* __restrict__ g,
    const float* __restrict__ b, __half* __restrict__ oh)
{
    __shared__ float red[16];
    const int row = blockIdx.x, tid = threadIdx.x;
    const float* xr = xin + (size_t)row * EMBED;
    const size_t ro = (size_t)row * EMBED;
    float v0 = xr[tid], v1 = xr[tid+256], v2 = xr[tid+512];
    float s = v0+v1+v2, s2 = v0*v0+v1*v1+v2*v2;
    #pragma unroll
    for (int o = 16; o; o >>= 1) {
        s  += __shfl_xor_sync(0xffffffffu, s,  o);
        s2 += __shfl_xor_sync(0xffffffffu, s2, o);
    }
    if ((tid & 31) == 0) { red[tid>>5] = s; red[8+(tid>>5)] = s2; }
    __syncthreads();
    float S=0.f, S2=0.f;
    #pragma unroll
    for (int i = 0; i < 8; i++) { S += red[i]; S2 += red[8+i]; }
    const float mean = S * (1.f/768.f);
    const float rstd = rsqrtf(S2*(1.f/768.f) - mean*mean + 1e-6f);
    oh[ro+tid]     = __float2half((v0-mean)*rstd*g[tid]     + b[tid]);
    oh[ro+tid+256] = __float2half((v1-mean)*rstd*g[tid+256] + b[tid+256]);
    oh[ro+tid+512] = __float2half((v2-mean)*rstd*g[tid+512] + b[tid+512]);
}

// ---------------------------------------------------------------------------
// HMMA GEMM (single-pass fp16): C[M,N] = A[M,K] @ B[N,K]^T (+bias).
// CTA 128x128, 8 warps of 64x32, K-chunk 32, double-buffered cp.async smem.
// M % 128 == 0, N % 128 == 0, K % 32 == 0.
// EPI: 0 bias->fp32 | 1 bias+gelu->fp16 | 2 bias+res->fp32
// ---------------------------------------------------------------------------
#define LDA        40                      // halves per smem row
#define ARR_BYTES  (128*LDA*2)             // 10240
#define BUF_BYTES  (2*ARR_BYTES)           // A + B = 20480
#define GSM_BYTES  (2*BUF_BYTES)           // 40960

template<int EPI>
__global__ __launch_bounds__(256, 2) void tgemm(
    const __half* __restrict__ A, const __half* __restrict__ B,
    const float* __restrict__ bias, float* __restrict__ Co,
    __half* __restrict__ Ch, int M, int N, int K, const float* __restrict__ res)
{
    extern __shared__ char smc[];
    const uint32_t smb = s2u(smc);
    const int tid = threadIdx.x;
    const int wid = tid >> 5, lane = tid & 31;
    const int bm = blockIdx.y * 128, bn = blockIdx.x * 128;
    const int wm = wid & 1, wn = wid >> 1;      // warp tile: 64 (M) x 32 (N)
    const int NC = K >> 5;

    float acc[4][4][4];
    #pragma unroll
    for (int i = 0; i < 4; i++)
        #pragma unroll
        for (int j = 0; j < 4; j++)
            #pragma unroll
            for (int k = 0; k < 4; k++) acc[i][j][k] = 0.f;

    const uint32_t offA = (uint32_t)((wm*64 + (lane & 7) + 8*((lane >> 3) & 1)) * LDA
                                     + 8*(lane >> 4)) * 2;
    const uint32_t offB = (uint32_t)((wn*32 + (lane & 7) + 8*(lane >> 4)) * LDA
                                     + 8*((lane >> 3) & 1)) * 2;

    auto load_chunk = [&](int c, int b) {
        const int k0 = c << 5;
        const uint32_t bb = smb + b * BUF_BYTES;
        #pragma unroll
        for (int a = 0; a < 2; a++) {
            const __half* G = a ? B : A;
            const int gb = a ? bn : bm;
            const uint32_t ab = bb + a * ARR_BYTES;
            #pragma unroll
            for (int s = 0; s < 2; s++) {
                const int u = tid + s * 256;        // [0,512)
                const int row = u >> 2, seg = u & 3;
                cp16(ab + (uint32_t)(row * LDA + seg * 8) * 2,
                     G + (size_t)(gb + row) * K + k0 + seg * 8);
            }
        }
        cp_commit();
    };

    load_chunk(0, 0);

    for (int c = 0; c < NC; c++) {
        const int b = c & 1;
        if (c + 1 < NC) {
            load_chunk(c + 1, b ^ 1);
            asm volatile("cp.async.wait_group 1;");
        } else {
            asm volatile("cp.async.wait_group 0;");
        }
        __syncthreads();

        const uint32_t bb = smb + b * BUF_BYTES;
        const uint32_t pA = bb + offA;
        const uint32_t pB = bb + ARR_BYTES + offB;

        #pragma unroll
        for (int ks = 0; ks < 2; ks++) {
            const uint32_t kso = ks * 32;           // 16 halves = 32 bytes
            uint32_t ah[4][4], bh[4][2];
            #pragma unroll
            for (int mt = 0; mt < 4; mt++)
                ldsm_x4(ah[mt][0], ah[mt][1], ah[mt][2], ah[mt][3],
                        pA + kso + mt * (16*LDA*2));
            #pragma unroll
            for (int L = 0; L < 2; L++)
                ldsm_x4(bh[2*L][0], bh[2*L][1], bh[2*L+1][0], bh[2*L+1][1],
                        pB + kso + L * (16*LDA*2));
            #pragma unroll
            for (int mt = 0; mt < 4; mt++)
                #pragma unroll
                for (int nt = 0; nt < 4; nt++)
                    mma16816(acc[mt][nt], ah[mt], bh[nt][0], bh[nt][1]);
        }
        __syncthreads();
    }

    // -------- epilogue --------
    const int rbase = bm + wm*64;
    const int nbase = bn + wn*32;
    #pragma unroll
    for (int mt = 0; mt < 4; mt++) {
        #pragma unroll
        for (int half = 0; half < 2; half++) {
            const int m = rbase + mt*16 + (lane >> 2) + half*8;
            #pragma unroll
            for (int nt = 0; nt < 4; nt++) {
                const int n = nbase + nt*8 + (lane & 3)*2;
                float v0 = acc[mt][nt][half*2 + 0] + bias[n];
                float v1 = acc[mt][nt][half*2 + 1] + bias[n + 1];
                if (EPI == 0) {
                    *(float2*)(Co + (size_t)m * N + n) = make_float2(v0, v1);
                } else if (EPI == 1) {
                    __half2 H;
                    H.x = __float2half(gelu_f(v0));
                    H.y = __float2half(gelu_f(v1));
                    *(__half2*)(Ch + (size_t)m * N + n) = H;
                } else {
                    const float2 r2 = *(const float2*)(res + (size_t)m * N + n);
                    *(float2*)(Co + (size_t)m * N + n) = make_float2(v0 + r2.x, v1 + r2.y);
                }
            }
        }
    }
}

// ---------------------------------------------------------------------------
// Window attention. QKV is COMPACT (x-layout); padded tokens use b_qkv
// (matches zero-padded LN rows through the projection). Output scattered
// back to compact layout as fp16.
// ---------------------------------------------------------------------------
#define ATTN_SMEM_FLOATS (NTOK*68 + NTOK*68 + NTOK*64 + 27*64 + 27*64 + NTOK*14 + NTOK*14 + 8*2*NTOK)
#define ATTN_SMEM_BYTES  (ATTN_SMEM_FLOATS * 4)

__global__ __launch_bounds__(256) void attn_kernel(
    const float* __restrict__ qkv, const float* __restrict__ bqkv,
    const float* __restrict__ relh, const float* __restrict__ relw,
    __half* __restrict__ ao)
{
    extern __shared__ float sm[];
    float* Qs  = sm;
    float* Ks  = Qs  + NTOK * 68;
    float* Vs  = Ks  + NTOK * 68;
    float* Rh  = Vs  + NTOK * 64;
    float* Rw  = Rh  + 27 * 64;
    float* BHs = Rw  + 27 * 64;
    float* BWs = BHs + NTOK * 14;
    float* Ps  = BWs + NTOK * 14;

    const int tid = threadIdx.x;
    const int w = blockIdx.x / NHEAD, h = blockIdx.x % NHEAD;
    const int bI = w / 25, wr = w % 25;
    const int wy = wr / 5, wx = wr % 5;

    for (int idx = tid; idx < NTOK * 16; idx += 256) {
        const int t = idx >> 4, c4 = (idx & 15) << 2;
        const int y = wy * 14 + t / 14, xx = wx * 14 + t % 14;
        const float* rp = (y < 64 && xx < 64)
            ? qkv + (size_t)((bI * 64 + y) * 64 + xx) * QKVN + h * HD
            : bqkv + h * HD;
        float4 q4 = *(const float4*)(rp + c4);
        float4 k4 = *(const float4*)(rp + 768 + c4);
        float4 v4 = *(const float4*)(rp + 1536 + c4);
        *(float4*)&Qs[t * 68 + c4] = q4;
        *(float4*)&Ks[t * 68 + c4] = k4;
        *(float4*)&Vs[t * 64 + c4] = v4;
    }
    for (int idx = tid; idx < 27 * 64; idx += 256) { Rh[idx] = relh[idx]; Rw[idx] = relw[idx]; }
    __syncthreads();

    const int wid = tid >> 5, lane = tid & 31;

    for (int i = wid; i < NTOK; i += 8) {
        const int p = i / 14, qc = i % 14;
        const float2 q2 = *(const float2*)&Qs[i * 68 + 2 * lane];
        float acch[14], accw[14];
        #pragma unroll
        for (int r = 0; r < 14; r++) {
            const float2 rh2 = *(const float2*)&Rh[(p  + 13 - r) * 64 + 2 * lane];
            const float2 rw2 = *(const float2*)&Rw[(qc + 13 - r) * 64 + 2 * lane];
            acch[r] = q2.x * rh2.x + q2.y * rh2.y;
            accw[r] = q2.x * rw2.x + q2.y * rw2.y;
        }
        #pragma unroll
        for (int o = 16; o; o >>= 1) {
            #pragma unroll
            for (int r = 0; r < 14; r++) {
                acch[r] += __shfl_xor_sync(0xffffffffu, acch[r], o);
                accw[r] += __shfl_xor_sync(0xffffffffu, accw[r], o);
            }
        }
        if (lane == 0) {
            #pragma unroll
            for (int r = 0; r < 14; r++) { BHs[i*14+r] = acch[r]; BWs[i*14+r] = accw[r]; }
        }
    }
    __syncthreads();

    const float SCALE = 0.125f;
    float* P0 = Ps + wid * (2 * NTOK);
    float* P1 = P0 + NTOK;

    for (int i0 = wid * 2; i0 < NTOK; i0 += 16) {
        const int i1 = i0 + 1;
        const float* q0p = &Qs[i0 * 68];
        const float* q1p = &Qs[i1 * 68];
        float s0[7], s1[7];
        float mx0 = -1e30f, mx1 = -1e30f;
        #pragma unroll
        for (int jj = 0; jj < 7; jj++) {
            const int j = jj * 32 + lane;
            float a0 = -1e30f, a1 = -1e30f;
            if (j < NTOK) {
                const float* kr = &Ks[j * 68];
                float d0 = 0.f, d1 = 0.f;
                #pragma unroll
                for (int d = 0; d < 64; d += 4) {
                    float4 k4 = *(const float4*)(kr + d);
                    float4 qa = *(const float4*)(q0p + d);
                    float4 qb = *(const float4*)(q1p + d);
                    d0 += qa.x*k4.x + qa.y*k4.y + qa.z*k4.z + qa.w*k4.w;
                    d1 += qb.x*k4.x + qb.y*k4.y + qb.z*k4.z + qb.w*k4.w;
                }
                const int jp = j / 14, jq = j % 14;
                a0 = d0 * SCALE + BHs[i0*14+jp] + BWs[i0*14+jq];
                a1 = d1 * SCALE + BHs[i1*14+jp] + BWs[i1*14+jq];
            }
            s0[jj] = a0; s1[jj] = a1;
            mx0 = fmaxf(mx0, a0); mx1 = fmaxf(mx1, a1);
        }
        #pragma unroll
        for (int o = 16; o; o >>= 1) {
            mx0 = fmaxf(mx0, __shfl_xor_sync(0xffffffffu, mx0, o));
            mx1 = fmaxf(mx1, __shfl_xor_sync(0xffffffffu, mx1, o));
        }
        float sum0 = 0.f, sum1 = 0.f;
        #pragma unroll
        for (int jj = 0; jj < 7; jj++) {
            float e0 = __expf(s0[jj] - mx0);
            float e1 = __expf(s1[jj] - mx1);
            if (jj * 32 + lane >= NTOK) { e0 = 0.f; e1 = 0.f; }
            s0[jj] = e0; s1[jj] = e1;
            sum0 += e0; sum1 += e1;
        }
        #pragma unroll
        for (int o = 16; o; o >>= 1) {
            sum0 += __shfl_xor_sync(0xffffffffu, sum0, o);
            sum1 += __shfl_xor_sync(0xffffffffu, sum1, o);
        }
        const float r0 = 1.f / sum0, r1 = 1.f / sum1;
        #pragma unroll
        for (int jj = 0; jj < 7; jj++) {
            const int j = jj * 32 + lane;
            if (j < NTOK) { P0[j] = s0[jj] * r0; P1[j] = s1[jj] * r1; }
        }
        __syncwarp();
        float o00 = 0.f, o01 = 0.f, o10 = 0.f, o11 = 0.f;
        #pragma unroll 7
        for (int j4 = 0; j4 < 49; j4++) {
            const float4 p0 = *(const float4*)(P0 + j4 * 4);
            const float4 p1 = *(const float4*)(P1 + j4 * 4);
            const float* vb = &Vs[j4 * 4 * 64 + 2 * lane];
            const float2 v0 = *(const float2*)(vb);
            const float2 v1 = *(const float2*)(vb + 64);
            const float2 v2 = *(const float2*)(vb + 128);
            const float2 v3 = *(const float2*)(vb + 192);
            o00 += p0.x*v0.x + p0.y*v1.x + p0.z*v2.x + p0.w*v3.x;
            o01 += p0.x*v0.y + p0.y*v1.y + p0.z*v2.y + p0.w*v3.y;
            o10 += p1.x*v0.x + p1.y*v1.x + p1.z*v2.x + p1.w*v3.x;
            o11 += p1.x*v0.y + p1.y*v1.y + p1.z*v2.y + p1.w*v3.y;
        }
        // scatter to compact layout, skipping padded tokens
        const int y0 = wy*14 + i0/14, x0 = wx*14 + i0%14;
        const int y1 = wy*14 + i1/14, x1p = wx*14 + i1%14;
        if (y0 < 64 && x0 < 64) {
            const size_t ro = (size_t)((bI*64 + y0)*64 + x0) * EMBED + h * HD + 2*lane;
            __half2 H; H.x = __float2half(o00); H.y = __float2half(o01);
            *(__half2*)(ao + ro) = H;
        }
        if (y1 < 64 && x1p < 64) {
            const size_t ro = (size_t)((bI*64 + y1)*64 + x1p) * EMBED + h * HD + 2*lane;
            __half2 H; H.x = __float2half(o10); H.y = __float2half(o11);
            *(__half2*)(ao + ro) = H;
        }
        __syncwarp();
    }
}

// ---------------------------------------------------------------------------
// kernel_launch
// ---------------------------------------------------------------------------
extern "C" void kernel_launch(void* const* d_in, const int* in_sizes, int n_in,
                              void* d_out, int out_size)
{
    const float* x      = (const float*)d_in[0];
    const float* g1     = (const float*)d_in[1];
    const float* beta1  = (const float*)d_in[2];
    const float* w_qkv  = (const float*)d_in[3];
    const float* b_qkv  = (const float*)d_in[4];
    const float* w_proj = (const float*)d_in[5];
    const float* b_proj = (const float*)d_in[6];
    const float* relh   = (const float*)d_in[7];
    const float* relw   = (const float*)d_in[8];
    const float* g2     = (const float*)d_in[9];
    const float* beta2  = (const float*)d_in[10];
    const float* w_fc1  = (const float*)d_in[11];
    const float* b_fc1  = (const float*)d_in[12];
    const float* w_fc2  = (const float*)d_in[13];
    const float* b_fc2  = (const float*)d_in[14];
    float* out = (float*)d_out;

    __half *hwin, *attn, *h2, *ff, *wqkv, *wprj, *wf1, *wf2;
    float *qkv, *x1;
    cudaGetSymbolAddress((void**)&hwin, g_hwin);
    cudaGetSymbolAddress((void**)&qkv,  g_qkv);
    cudaGetSymbolAddress((void**)&attn, g_attn);
    cudaGetSymbolAddress((void**)&x1,   g_x1);
    cudaGetSymbolAddress((void**)&h2,   g_h2);
    cudaGetSymbolAddress((void**)&ff,   g_ff);
    cudaGetSymbolAddress((void**)&wqkv, g_wqkv);
    cudaGetSymbolAddress((void**)&wprj, g_wprj);
    cudaGetSymbolAddress((void**)&wf1,  g_wfc1);
    cudaGetSymbolAddress((void**)&wf2,  g_wfc2);

    cudaFuncSetAttribute(attn_kernel, cudaFuncAttributeMaxDynamicSharedMemorySize, ATTN_SMEM_BYTES);
    cudaFuncSetAttribute(tgemm<0>, cudaFuncAttributeMaxDynamicSharedMemorySize, GSM_BYTES);
    cudaFuncSetAttribute(tgemm<1>, cudaFuncAttributeMaxDynamicSharedMemorySize, GSM_BYTES);
    cudaFuncSetAttribute(tgemm<2>, cudaFuncAttributeMaxDynamicSharedMemorySize, GSM_BYTES);

    // 1. LN1 (compact layout)   [launch 0]
    ln_kernel<<<M_TOK, 256>>>(x, g1, beta1, hwin);

    // weight prep (transpose + fp16)   [launches 1-4]
    wprep<<<dim3(QKVN/32, EMBED/32), 256>>>(w_qkv,  wqkv, EMBED, QKVN);
    wprep<<<dim3(EMBED/32, EMBED/32), 256>>>(w_proj, wprj, EMBED, EMBED);
    wprep<<<dim3(FFDIM/32, EMBED/32), 256>>>(w_fc1,  wf1,  EMBED, FFDIM);
    wprep<<<dim3(EMBED/32, FFDIM/32), 256>>>(w_fc2,  wf2,  FFDIM, EMBED);

    // 2. QKV projection (compact, M=32768)   [launch 5 -> ncu capture target]
    tgemm<0><<<dim3(QKVN/128, M_TOK/128), 256, GSM_BYTES>>>(
        hwin, wqkv, b_qkv, qkv, nullptr, M_TOK, QKVN, EMBED, nullptr);

    // 3. Window attention (gather + scatter inside)
    attn_kernel<<<NWIN * NHEAD, 256, ATTN_SMEM_BYTES>>>(qkv, b_qkv, relh, relw, attn);

    // 4. proj + residual: x1 = x + attn @ w_proj + b_proj
    tgemm<2><<<dim3(EMBED/128, M_TOK/128), 256, GSM_BYTES>>>(
        attn, wprj, b_proj, x1, nullptr, M_TOK, EMBED, EMBED, x);

    // 5. LN2
    ln_kernel<<<M_TOK, 256>>>(x1, g2, beta2, h2);

    // 6. fc1 + GELU -> fp16
    tgemm<1><<<dim3(FFDIM/128, M_TOK/128), 256, GSM_BYTES>>>(
        h2, wf1, b_fc1, nullptr, ff, M_TOK, FFDIM, EMBED, nullptr);

    // 7. fc2 + residual -> out
    tgemm<2><<<dim3(EMBED/128, M_TOK/128), 256, GSM_BYTES>>>(
        ff, wf2, b_fc2, out, nullptr, M_TOK, EMBED, FFDIM, x1);
}

// round 12
// speedup vs baseline: 2.5390x; 1.4436x over previous
#include <cuda_runtime.h>
#include <cuda_fp16.h>
#include <math.h>
#include <stdint.h>

// ---------------------------------------------------------------------------
// Problem constants
// ---------------------------------------------------------------------------
#define EMBED  768
#define NWIN   200
#define NTOK   196
#define NHEAD  12
#define HD     64
#define M_TOK  32768
#define FFDIM  3072
#define QKVN   2304

// ---------------------------------------------------------------------------
// Scratch (device globals; no allocation allowed)
// ---------------------------------------------------------------------------
__device__ __half g_hwin[(size_t)M_TOK*EMBED];
__device__ __half g_qkv [(size_t)M_TOK*QKVN];
__device__ __half g_attn[(size_t)M_TOK*EMBED];
__device__ float  g_x1  [(size_t)M_TOK*EMBED];
__device__ __half g_h2  [(size_t)M_TOK*EMBED];
__device__ __half g_ff  [(size_t)M_TOK*FFDIM];
__device__ __half g_bq16[QKVN];
// transposed fp16 weights: [N][K]
__device__ __half g_wqkv[(size_t)QKVN*EMBED];
__device__ __half g_wprj[(size_t)EMBED*EMBED];
__device__ __half g_wfc1[(size_t)FFDIM*EMBED];
__device__ __half g_wfc2[(size_t)EMBED*FFDIM];

// ---------------------------------------------------------------------------
// Helpers
// ---------------------------------------------------------------------------
__device__ __forceinline__ float gelu_f(float v) {
    return 0.5f * v * (1.0f + erff(v * 0.7071067811865476f));
}
__device__ __forceinline__ uint32_t s2u(const void* p) {
    uint32_t a;
    asm("{ .reg .u64 t; cvta.to.shared.u64 t, %1; cvt.u32.u64 %0, t; }" : "=r"(a) : "l"(p));
    return a;
}
__device__ __forceinline__ void ldsm_x4(uint32_t& r0, uint32_t& r1, uint32_t& r2,
                                        uint32_t& r3, uint32_t addr) {
    asm volatile("ldmatrix.sync.aligned.m8n8.x4.shared.b16 {%0,%1,%2,%3}, [%4];"
                 : "=r"(r0), "=r"(r1), "=r"(r2), "=r"(r3) : "r"(addr));
}
__device__ __forceinline__ void ldsm_x4t(uint32_t& r0, uint32_t& r1, uint32_t& r2,
                                         uint32_t& r3, uint32_t addr) {
    asm volatile("ldmatrix.sync.aligned.m8n8.x4.trans.shared.b16 {%0,%1,%2,%3}, [%4];"
                 : "=r"(r0), "=r"(r1), "=r"(r2), "=r"(r3) : "r"(addr));
}
__device__ __forceinline__ void mma16816(float* c, const uint32_t* a,
                                         uint32_t b0, uint32_t b1) {
    asm volatile(
        "mma.sync.aligned.m16n8k16.row.col.f32.f16.f16.f32 "
        "{%0,%1,%2,%3}, {%4,%5,%6,%7}, {%8,%9}, {%0,%1,%2,%3};"
        : "+f"(c[0]), "+f"(c[1]), "+f"(c[2]), "+f"(c[3])
        : "r"(a[0]), "r"(a[1]), "r"(a[2]), "r"(a[3]), "r"(b0), "r"(b1));
}
__device__ __forceinline__ void cp16(uint32_t saddr, const void* g) {
    asm volatile("cp.async.cg.shared.global [%0], [%1], 16;" :: "r"(saddr), "l"(g));
}
__device__ __forceinline__ void cp_commit() {
    asm volatile("cp.async.commit_group;");
}
__device__ __forceinline__ uint32_t packh2(float a, float b) {
    __half2 h = __floats2half2_rn(a, b);
    return *reinterpret_cast<uint32_t*>(&h);
}

// ---------------------------------------------------------------------------
// Weight prep: transpose [K,N] fp32 -> [N,K] fp16
// ---------------------------------------------------------------------------
__global__ __launch_bounds__(256) void wprep(
    const float* __restrict__ W, __half* __restrict__ T, int K, int N)
{
    __shared__ float t[32][33];
    const int n0 = blockIdx.x * 32, k0 = blockIdx.y * 32;
    const int tx = threadIdx.x & 31, ty = threadIdx.x >> 5;
    #pragma unroll
    for (int i = 0; i < 32; i += 8)
        t[ty + i][tx] = W[(size_t)(k0 + ty + i) * N + n0 + tx];
    __syncthreads();
    #pragma unroll
    for (int i = 0; i < 32; i += 8)
        T[(size_t)(n0 + ty + i) * K + k0 + tx] = __float2half(t[tx][ty + i]);
}

__global__ void bprep(const float* __restrict__ b, __half* __restrict__ o, int n) {
    int i = blockIdx.x * 256 + threadIdx.x;
    if (i < n) o[i] = __float2half(b[i]);
}

// ---------------------------------------------------------------------------
// LayerNorm -> fp16
// ---------------------------------------------------------------------------
__global__ __launch_bounds__(256) void ln_kernel(
    const float* __restrict__ xin, const float* __restrict__ g,
    const float* __restrict__ b, __half* __restrict__ oh)
{
    __shared__ float red[16];
    const int row = blockIdx.x, tid = threadIdx.x;
    const float* xr = xin + (size_t)row * EMBED;
    const size_t ro = (size_t)row * EMBED;
    float v0 = xr[tid], v1 = xr[tid+256], v2 = xr[tid+512];
    float s = v0+v1+v2, s2 = v0*v0+v1*v1+v2*v2;
    #pragma unroll
    for (int o = 16; o; o >>= 1) {
        s  += __shfl_xor_sync(0xffffffffu, s,  o);
        s2 += __shfl_xor_sync(0xffffffffu, s2, o);
    }
    if ((tid & 31) == 0) { red[tid>>5] = s; red[8+(tid>>5)] = s2; }
    __syncthreads();
    float S=0.f, S2=0.f;
    #pragma unroll
    for (int i = 0; i < 8; i++) { S += red[i]; S2 += red[8+i]; }
    const float mean = S * (1.f/768.f);
    const float rstd = rsqrtf(S2*(1.f/768.f) - mean*mean + 1e-6f);
    oh[ro+tid]     = __float2half((v0-mean)*rstd*g[tid]     + b[tid]);
    oh[ro+tid+256] = __float2half((v1-mean)*rstd*g[tid+256] + b[tid+256]);
    oh[ro+tid+512] = __float2half((v2-mean)*rstd*g[tid+512] + b[tid+512]);
}

// ---------------------------------------------------------------------------
// HMMA GEMM (fp16): C[M,N] = A[M,K] @ B[N,K]^T (+bias).
// CTA 128x128, 8 warps 64x32, K-chunk 32, double-buffered cp.async smem.
// EPI: 0 bias->fp32 | 1 bias+gelu->fp16 | 2 bias+res->fp32 | 3 bias->fp16
// ---------------------------------------------------------------------------
#define LDA        40
#define ARR_BYTES  (128*LDA*2)
#define BUF_BYTES  (2*ARR_BYTES)
#define GSM_BYTES  (2*BUF_BYTES)

template<int EPI>
__global__ __launch_bounds__(256, 2) void tgemm(
    const __half* __restrict__ A, const __half* __restrict__ B,
    const float* __restrict__ bias, float* __restrict__ Co,
    __half* __restrict__ Ch, int M, int N, int K, const float* __restrict__ res)
{
    extern __shared__ char smc[];
    const uint32_t smb = s2u(smc);
    const int tid = threadIdx.x;
    const int wid = tid >> 5, lane = tid & 31;
    const int bm = blockIdx.y * 128, bn = blockIdx.x * 128;
    const int wm = wid & 1, wn = wid >> 1;
    const int NC = K >> 5;

    float acc[4][4][4];
    #pragma unroll
    for (int i = 0; i < 4; i++)
        #pragma unroll
        for (int j = 0; j < 4; j++)
            #pragma unroll
            for (int k = 0; k < 4; k++) acc[i][j][k] = 0.f;

    const uint32_t offA = (uint32_t)((wm*64 + (lane & 7) + 8*((lane >> 3) & 1)) * LDA
                                     + 8*(lane >> 4)) * 2;
    const uint32_t offB = (uint32_t)((wn*32 + (lane & 7) + 8*(lane >> 4)) * LDA
                                     + 8*((lane >> 3) & 1)) * 2;

    auto load_chunk = [&](int c, int b) {
        const int k0 = c << 5;
        const uint32_t bb = smb + b * BUF_BYTES;
        #pragma unroll
        for (int a = 0; a < 2; a++) {
            const __half* G = a ? B : A;
            const int gb = a ? bn : bm;
            const uint32_t ab = bb + a * ARR_BYTES;
            #pragma unroll
            for (int s = 0; s < 2; s++) {
                const int u = tid + s * 256;
                const int row = u >> 2, seg = u & 3;
                cp16(ab + (uint32_t)(row * LDA + seg * 8) * 2,
                     G + (size_t)(gb + row) * K + k0 + seg * 8);
            }
        }
        cp_commit();
    };

    load_chunk(0, 0);

    for (int c = 0; c < NC; c++) {
        const int b = c & 1;
        if (c + 1 < NC) {
            load_chunk(c + 1, b ^ 1);
            asm volatile("cp.async.wait_group 1;");
        } else {
            asm volatile("cp.async.wait_group 0;");
        }
        __syncthreads();

        const uint32_t bb = smb + b * BUF_BYTES;
        const uint32_t pA = bb + offA;
        const uint32_t pB = bb + ARR_BYTES + offB;

        #pragma unroll
        for (int ks = 0; ks < 2; ks++) {
            const uint32_t kso = ks * 32;
            uint32_t ah[4][4], bh[4][2];
            #pragma unroll
            for (int mt = 0; mt < 4; mt++)
                ldsm_x4(ah[mt][0], ah[mt][1], ah[mt][2], ah[mt][3],
                        pA + kso + mt * (16*LDA*2));
            #pragma unroll
            for (int L = 0; L < 2; L++)
                ldsm_x4(bh[2*L][0], bh[2*L][1], bh[2*L+1][0], bh[2*L+1][1],
                        pB + kso + L * (16*LDA*2));
            #pragma unroll
            for (int mt = 0; mt < 4; mt++)
                #pragma unroll
                for (int nt = 0; nt < 4; nt++)
                    mma16816(acc[mt][nt], ah[mt], bh[nt][0], bh[nt][1]);
        }
        __syncthreads();
    }

    const int rbase = bm + wm*64;
    const int nbase = bn + wn*32;
    #pragma unroll
    for (int mt = 0; mt < 4; mt++) {
        #pragma unroll
        for (int half = 0; half < 2; half++) {
            const int m = rbase + mt*16 + (lane >> 2) + half*8;
            #pragma unroll
            for (int nt = 0; nt < 4; nt++) {
                const int n = nbase + nt*8 + (lane & 3)*2;
                float v0 = acc[mt][nt][half*2 + 0] + bias[n];
                float v1 = acc[mt][nt][half*2 + 1] + bias[n + 1];
                if (EPI == 0) {
                    *(float2*)(Co + (size_t)m * N + n) = make_float2(v0, v1);
                } else if (EPI == 1) {
                    __half2 H;
                    H.x = __float2half(gelu_f(v0));
                    H.y = __float2half(gelu_f(v1));
                    *(__half2*)(Ch + (size_t)m * N + n) = H;
                } else if (EPI == 2) {
                    const float2 r2 = *(const float2*)(res + (size_t)m * N + n);
                    *(float2*)(Co + (size_t)m * N + n) = make_float2(v0 + r2.x, v1 + r2.y);
                } else {
                    __half2 H;
                    H.x = __float2half(v0); H.y = __float2half(v1);
                    *(__half2*)(Ch + (size_t)m * N + n) = H;
                }
            }
        }
    }
}

// ---------------------------------------------------------------------------
// FA2-style window attention on mma.sync. One (window, head) per CTA.
// qkv fp16 compact layout; gather (padded token -> b_qkv) and scatter inside.
// ---------------------------------------------------------------------------
#define LDH   72           // halves per smem row (144B; conflict-free ldsm)
#define NPAD  208          // tokens padded to 13 x m16
#define OFF_Q 0
#define OFF_K (NPAD*LDH*2)
#define OFF_V (2*NPAD*LDH*2)
#define OFF_RH (3*NPAD*LDH*2)          // 27*64 halves
#define OFF_RW (OFF_RH + 27*64*2)
#define OFF_BH (OFF_RW + 27*64*2)      // 196*14 halves
#define OFF_BW (OFF_BH + 196*14*2)
#define ATTN_SMEM (OFF_BW + 196*14*2)  // 107744 B

__global__ __launch_bounds__(256, 2) void attn_kernel(
    const __half* __restrict__ qkv, const __half* __restrict__ bq16,
    const float* __restrict__ relh, const float* __restrict__ relw,
    __half* __restrict__ ao)
{
    extern __shared__ char smc[];
    const uint32_t smb = s2u(smc);
    __half* Qh = (__half*)(smc + OFF_Q);
    __half* Kh = (__half*)(smc + OFF_K);
    __half* Vh = (__half*)(smc + OFF_V);
    __half* Rh = (__half*)(smc + OFF_RH);
    __half* Rw = (__half*)(smc + OFF_RW);
    __half* BH = (__half*)(smc + OFF_BH);
    __half* BW = (__half*)(smc + OFF_BW);

    const int tid = threadIdx.x;
    const int w = blockIdx.x / NHEAD, h = blockIdx.x % NHEAD;
    const int bI = w / 25, wr = w % 25;
    const int wy = wr / 5, wx = wr % 5;
    const int wid = tid >> 5, lane = tid & 31;

    // ---- load Q,K,V (fp16) with window gather; pad rows with zeros ----
    for (int idx = tid; idx < NTOK * 8; idx += 256) {
        const int t = idx >> 3, seg = idx & 7;
        const int y = wy * 14 + t / 14, xx = wx * 14 + t % 14;
        const __half* rp = (y < 64 && xx < 64)
            ? qkv + (size_t)((bI * 64 + y) * 64 + xx) * QKVN + h * HD + seg * 8
            : bq16 + h * HD + seg * 8;
        *(uint4*)&Qh[t * LDH + seg * 8] = *(const uint4*)(rp);
        *(uint4*)&Kh[t * LDH + seg * 8] = *(const uint4*)(rp + 768);
        *(uint4*)&Vh[t * LDH + seg * 8] = *(const uint4*)(rp + 1536);
    }
    for (int idx = tid; idx < (NPAD - NTOK) * 8; idx += 256) {
        const int t = NTOK + (idx >> 3), seg = idx & 7;
        const uint4 z = make_uint4(0, 0, 0, 0);
        *(uint4*)&Qh[t * LDH + seg * 8] = z;
        *(uint4*)&Kh[t * LDH + seg * 8] = z;
        *(uint4*)&Vh[t * LDH + seg * 8] = z;
    }
    for (int idx = tid; idx < 27 * 64; idx += 256) {
        Rh[idx] = __float2half(relh[idx]);
        Rw[idx] = __float2half(relw[idx]);
    }
    __syncthreads();

    // ---- decomposed rel-pos bias tables (fp32 compute, fp16 store) ----
    for (int i = wid; i < NTOK; i += 8) {
        const int p = i / 14, qc = i % 14;
        const __half2 qh2 = *(const __half2*)&Qh[i * LDH + 2 * lane];
        const float2 q2 = __half22float2(qh2);
        float acch[14], accw[14];
        #pragma unroll
        for (int r = 0; r < 14; r++) {
            const float2 rh2 = __half22float2(*(const __half2*)&Rh[(p  + 13 - r) * 64 + 2 * lane]);
            const float2 rw2 = __half22float2(*(const __half2*)&Rw[(qc + 13 - r) * 64 + 2 * lane]);
            acch[r] = q2.x * rh2.x + q2.y * rh2.y;
            accw[r] = q2.x * rw2.x + q2.y * rw2.y;
        }
        #pragma unroll
        for (int o = 16; o; o >>= 1) {
            #pragma unroll
            for (int r = 0; r < 14; r++) {
                acch[r] += __shfl_xor_sync(0xffffffffu, acch[r], o);
                accw[r] += __shfl_xor_sync(0xffffffffu, accw[r], o);
            }
        }
        if (lane == 0) {
            #pragma unroll
            for (int r = 0; r < 14; r++) {
                BH[i*14+r] = __float2half(acch[r]);
                BW[i*14+r] = __float2half(accw[r]);
            }
        }
    }
    __syncthreads();

    const float SCALE = 0.125f;
    const uint32_t qb = smb + OFF_Q, kb = smb + OFF_K, vb = smb + OFF_V;

    // ---- per m16 tile: online-softmax FA loop over 13 key chunks of 16 ----
    for (int tile = wid; tile < 13; tile += 8) {
        uint32_t aq[4][4];
        #pragma unroll
        for (int kk = 0; kk < 4; kk++)
            ldsm_x4(aq[kk][0], aq[kk][1], aq[kk][2], aq[kk][3],
                    qb + (uint32_t)((tile*16 + (lane&7) + 8*((lane>>3)&1)) * LDH
                                    + kk*16 + 8*(lane>>4)) * 2);

        float o[8][4];
        #pragma unroll
        for (int i = 0; i < 8; i++)
            #pragma unroll
            for (int j = 0; j < 4; j++) o[i][j] = 0.f;
        float mrun0 = -1e30f, mrun1 = -1e30f, lrun0 = 0.f, lrun1 = 0.f;

        const int i0 = tile*16 + (lane >> 2);
        const int i0c = (i0 < NTOK ? i0 : 0), i1c = (i0 + 8 < NTOK ? i0 + 8 : 0);

        for (int kc = 0; kc < 13; kc++) {
            float S0[4], S1[4];
            #pragma unroll
            for (int j = 0; j < 4; j++) { S0[j] = 0.f; S1[j] = 0.f; }
            #pragma unroll
            for (int kk = 0; kk < 4; kk++) {
                uint32_t r0, r1, r2, r3;
                ldsm_x4(r0, r1, r2, r3,
                        kb + (uint32_t)((kc*16 + (lane&7) + 8*(lane>>4)) * LDH
                                        + kk*16 + 8*((lane>>3)&1)) * 2);
                mma16816(S0, aq[kk], r0, r1);
                mma16816(S1, aq[kk], r2, r3);
            }
            // scale + bias + mask; columns per thread: j0,j0+1 (t0) j0+8,j0+9 (t1)
            const int j0 = kc*16 + 2*(lane & 3);
            float s[2][4];       // [row 0/+8][e: t0c0,t0c1,t1c0,t1c1]
            #pragma unroll
            for (int e = 0; e < 4; e++) {
                const int j = j0 + (e & 1) + (e >> 1) * 8;
                float b0, b1;
                bool ok = (j < NTOK);
                int jp = 0, jq = 0;
                if (ok) { jp = j / 14; jq = j - jp * 14; }
                b0 = __half2float(BH[i0c*14+jp]) + __half2float(BW[i0c*14+jq]);
                b1 = __half2float(BH[i1c*14+jp]) + __half2float(BW[i1c*14+jq]);
                const float r0v = (e >> 1) ? S1[e & 1] : S0[e & 1];
                const float r1v = (e >> 1) ? S1[2 + (e & 1)] : S0[2 + (e & 1)];
                s[0][e] = ok ? r0v * SCALE + b0 : -1e30f;
                s[1][e] = ok ? r1v * SCALE + b1 : -1e30f;
            }
            // row max (4 lanes per row)
            float mx0 = fmaxf(fmaxf(s[0][0], s[0][1]), fmaxf(s[0][2], s[0][3]));
            float mx1 = fmaxf(fmaxf(s[1][0], s[1][1]), fmaxf(s[1][2], s[1][3]));
            mx0 = fmaxf(mx0, __shfl_xor_sync(0xffffffffu, mx0, 1));
            mx0 = fmaxf(mx0, __shfl_xor_sync(0xffffffffu, mx0, 2));
            mx1 = fmaxf(mx1, __shfl_xor_sync(0xffffffffu, mx1, 1));
            mx1 = fmaxf(mx1, __shfl_xor_sync(0xffffffffu, mx1, 2));
            const float mn0 = fmaxf(mrun0, mx0), mn1 = fmaxf(mrun1, mx1);
            const float sc0 = __expf(mrun0 - mn0), sc1 = __expf(mrun1 - mn1);
            float p[2][4], rs0 = 0.f, rs1 = 0.f;
            #pragma unroll
            for (int e = 0; e < 4; e++) {
                p[0][e] = __expf(s[0][e] - mn0);
                p[1][e] = __expf(s[1][e] - mn1);
                rs0 += p[0][e]; rs1 += p[1][e];
            }
            rs0 += __shfl_xor_sync(0xffffffffu, rs0, 1);
            rs0 += __shfl_xor_sync(0xffffffffu, rs0, 2);
            rs1 += __shfl_xor_sync(0xffffffffu, rs1, 1);
            rs1 += __shfl_xor_sync(0xffffffffu, rs1, 2);
            lrun0 = lrun0 * sc0 + rs0;
            lrun1 = lrun1 * sc1 + rs1;
            mrun0 = mn0; mrun1 = mn1;
            #pragma unroll
            for (int dt = 0; dt < 8; dt++) {
                o[dt][0] *= sc0; o[dt][1] *= sc0;
                o[dt][2] *= sc1; o[dt][3] *= sc1;
            }
            // P accum -> A-fragment (m16k16, k = this chunk's 16 keys)
            uint32_t ap[4];
            ap[0] = packh2(p[0][0], p[0][1]);
            ap[1] = packh2(p[1][0], p[1][1]);
            ap[2] = packh2(p[0][2], p[0][3]);
            ap[3] = packh2(p[1][2], p[1][3]);
            // PV: V chunk via ldmatrix.trans
            #pragma unroll
            for (int nn = 0; nn < 4; nn++) {
                uint32_t r0, r1, r2, r3;
                ldsm_x4t(r0, r1, r2, r3,
                         vb + (uint32_t)((kc*16 + (lane & 15)) * LDH
                                         + nn*16 + 8*(lane>>4)) * 2);
                mma16816(o[2*nn],     ap, r0, r1);
                mma16816(o[2*nn + 1], ap, r2, r3);
            }
        }

        // ---- write out (scatter to compact layout) ----
        const float inv0 = 1.f / lrun0, inv1 = 1.f / lrun1;
        #pragma unroll
        for (int half = 0; half < 2; half++) {
            const int i = tile*16 + (lane >> 2) + half*8;
            if (i >= NTOK) continue;
            const int y = wy*14 + i/14, xx = wx*14 + i%14;
            if (y >= 64 || xx >= 64) continue;
            __half* orow = ao + (size_t)((bI*64 + y)*64 + xx) * EMBED + h * HD;
            const float inv = half ? inv1 : inv0;
            #pragma unroll
            for (int dt = 0; dt < 8; dt++) {
                __half2 H;
                H.x = __float2half(o[dt][half*2 + 0] * inv);
                H.y = __float2half(o[dt][half*2 + 1] * inv);
                *(__half2*)(orow + dt*8 + 2*(lane & 3)) = H;
            }
        }
    }
}

// ---------------------------------------------------------------------------
// kernel_launch
// ---------------------------------------------------------------------------
extern "C" void kernel_launch(void* const* d_in, const int* in_sizes, int n_in,
                              void* d_out, int out_size)
{
    const float* x      = (const float*)d_in[0];
    const float* g1     = (const float*)d_in[1];
    const float* beta1  = (const float*)d_in[2];
    const float* w_qkv  = (const float*)d_in[3];
    const float* b_qkv  = (const float*)d_in[4];
    const float* w_proj = (const float*)d_in[5];
    const float* b_proj = (const float*)d_in[6];
    const float* relh   = (const float*)d_in[7];
    const float* relw   = (const float*)d_in[8];
    const float* g2     = (const float*)d_in[9];
    const float* beta2  = (const float*)d_in[10];
    const float* w_fc1  = (const float*)d_in[11];
    const float* b_fc1  = (const float*)d_in[12];
    const float* w_fc2  = (const float*)d_in[13];
    const float* b_fc2  = (const float*)d_in[14];
    float* out = (float*)d_out;

    __half *hwin, *qkv, *attn, *h2, *ff, *bq16, *wqkv, *wprj, *wf1, *wf2;
    float *x1;
    cudaGetSymbolAddress((void**)&hwin, g_hwin);
    cudaGetSymbolAddress((void**)&qkv,  g_qkv);
    cudaGetSymbolAddress((void**)&attn, g_attn);
    cudaGetSymbolAddress((void**)&x1,   g_x1);
    cudaGetSymbolAddress((void**)&h2,   g_h2);
    cudaGetSymbolAddress((void**)&ff,   g_ff);
    cudaGetSymbolAddress((void**)&bq16, g_bq16);
    cudaGetSymbolAddress((void**)&wqkv, g_wqkv);
    cudaGetSymbolAddress((void**)&wprj, g_wprj);
    cudaGetSymbolAddress((void**)&wf1,  g_wfc1);
    cudaGetSymbolAddress((void**)&wf2,  g_wfc2);

    cudaFuncSetAttribute(attn_kernel, cudaFuncAttributeMaxDynamicSharedMemorySize, ATTN_SMEM);
    cudaFuncSetAttribute(tgemm<1>, cudaFuncAttributeMaxDynamicSharedMemorySize, GSM_BYTES);
    cudaFuncSetAttribute(tgemm<2>, cudaFuncAttributeMaxDynamicSharedMemorySize, GSM_BYTES);
    cudaFuncSetAttribute(tgemm<3>, cudaFuncAttributeMaxDynamicSharedMemorySize, GSM_BYTES);

    // [0] LN1
    ln_kernel<<<M_TOK, 256>>>(x, g1, beta1, hwin);

    // [1-4] weight prep
    wprep<<<dim3(QKVN/32, EMBED/32), 256>>>(w_qkv,  wqkv, EMBED, QKVN);
    wprep<<<dim3(EMBED/32, EMBED/32), 256>>>(w_proj, wprj, EMBED, EMBED);
    wprep<<<dim3(FFDIM/32, EMBED/32), 256>>>(w_fc1,  wf1,  EMBED, FFDIM);
    wprep<<<dim3(EMBED/32, FFDIM/32), 256>>>(w_fc2,  wf2,  FFDIM, EMBED);

    // [5] QKV projection -> fp16 (ncu capture target)
    tgemm<3><<<dim3(QKVN/128, M_TOK/128), 256, GSM_BYTES>>>(
        hwin, wqkv, b_qkv, nullptr, qkv, M_TOK, QKVN, EMBED, nullptr);

    // [6] bias -> fp16
    bprep<<<(QKVN + 255)/256, 256>>>(b_qkv, bq16, QKVN);

    // [7] window attention (tensor-core FA)
    attn_kernel<<<NWIN * NHEAD, 256, ATTN_SMEM>>>(qkv, bq16, relh, relw, attn);

    // [8] proj + residual: x1 = x + attn @ w_proj + b_proj
    tgemm<2><<<dim3(EMBED/128, M_TOK/128), 256, GSM_BYTES>>>(
        attn, wprj, b_proj, x1, nullptr, M_TOK, EMBED, EMBED, x);

    // [9] LN2
    ln_kernel<<<M_TOK, 256>>>(x1, g2, beta2, h2);

    // [10] fc1 + GELU -> fp16
    tgemm<1><<<dim3(FFDIM/128, M_TOK/128), 256, GSM_BYTES>>>(
        h2, wf1, b_fc1, nullptr, ff, M_TOK, FFDIM, EMBED, nullptr);

    // [11] fc2 + residual -> out
    tgemm<2><<<dim3(EMBED/128, M_TOK/128), 256, GSM_BYTES>>>(
        ff, wf2, b_fc2, out, nullptr, M_TOK, EMBED, FFDIM, x1);
}

// round 13
// speedup vs baseline: 3.1021x; 1.2218x over previous
#include <cuda_runtime.h>
#include <cuda_fp16.h>
#include <math.h>
#include <stdint.h>

// ---------------------------------------------------------------------------
// Problem constants
// ---------------------------------------------------------------------------
#define EMBED  768
#define NWIN   200
#define NTOK   196
#define NHEAD  12
#define HD     64
#define M_TOK  32768
#define FFDIM  3072
#define QKVN   2304

// ---------------------------------------------------------------------------
// Scratch (device globals; no allocation allowed)
// ---------------------------------------------------------------------------
__device__ __half g_hwin[(size_t)M_TOK*EMBED];
__device__ __half g_qkv [(size_t)M_TOK*QKVN];
__device__ __half g_attn[(size_t)M_TOK*EMBED];
__device__ float  g_x1  [(size_t)M_TOK*EMBED];
__device__ __half g_h2  [(size_t)M_TOK*EMBED];
__device__ __half g_ff  [(size_t)M_TOK*FFDIM];
__device__ __half g_bq16[QKVN];
// transposed fp16 weights: [N][K]
__device__ __half g_wqkv[(size_t)QKVN*EMBED];
__device__ __half g_wprj[(size_t)EMBED*EMBED];
__device__ __half g_wfc1[(size_t)FFDIM*EMBED];
__device__ __half g_wfc2[(size_t)EMBED*FFDIM];

// ---------------------------------------------------------------------------
// Helpers
// ---------------------------------------------------------------------------
__device__ __forceinline__ float gelu_f(float v) {
    return 0.5f * v * (1.0f + erff(v * 0.7071067811865476f));
}
__device__ __forceinline__ uint32_t s2u(const void* p) {
    uint32_t a;
    asm("{ .reg .u64 t; cvta.to.shared.u64 t, %1; cvt.u32.u64 %0, t; }" : "=r"(a) : "l"(p));
    return a;
}
__device__ __forceinline__ void ldsm_x4(uint32_t& r0, uint32_t& r1, uint32_t& r2,
                                        uint32_t& r3, uint32_t addr) {
    asm volatile("ldmatrix.sync.aligned.m8n8.x4.shared.b16 {%0,%1,%2,%3}, [%4];"
                 : "=r"(r0), "=r"(r1), "=r"(r2), "=r"(r3) : "r"(addr));
}
__device__ __forceinline__ void ldsm_x4t(uint32_t& r0, uint32_t& r1, uint32_t& r2,
                                         uint32_t& r3, uint32_t addr) {
    asm volatile("ldmatrix.sync.aligned.m8n8.x4.trans.shared.b16 {%0,%1,%2,%3}, [%4];"
                 : "=r"(r0), "=r"(r1), "=r"(r2), "=r"(r3) : "r"(addr));
}
__device__ __forceinline__ void mma16816(float* c, const uint32_t* a,
                                         uint32_t b0, uint32_t b1) {
    asm volatile(
        "mma.sync.aligned.m16n8k16.row.col.f32.f16.f16.f32 "
        "{%0,%1,%2,%3}, {%4,%5,%6,%7}, {%8,%9}, {%0,%1,%2,%3};"
        : "+f"(c[0]), "+f"(c[1]), "+f"(c[2]), "+f"(c[3])
        : "r"(a[0]), "r"(a[1]), "r"(a[2]), "r"(a[3]), "r"(b0), "r"(b1));
}
__device__ __forceinline__ void cp16(uint32_t saddr, const void* g) {
    asm volatile("cp.async.cg.shared.global [%0], [%1], 16;" :: "r"(saddr), "l"(g));
}
__device__ __forceinline__ void cp_commit() {
    asm volatile("cp.async.commit_group;");
}
__device__ __forceinline__ uint32_t packh2(float a, float b) {
    __half2 h = __floats2half2_rn(a, b);
    return *reinterpret_cast<uint32_t*>(&h);
}

// ---------------------------------------------------------------------------
// Weight prep: transpose [K,N] fp32 -> [N,K] fp16
// ---------------------------------------------------------------------------
__global__ __launch_bounds__(256) void wprep(
    const float* __restrict__ W, __half* __restrict__ T, int K, int N)
{
    __shared__ float t[32][33];
    const int n0 = blockIdx.x * 32, k0 = blockIdx.y * 32;
    const int tx = threadIdx.x & 31, ty = threadIdx.x >> 5;
    #pragma unroll
    for (int i = 0; i < 32; i += 8)
        t[ty + i][tx] = W[(size_t)(k0 + ty + i) * N + n0 + tx];
    __syncthreads();
    #pragma unroll
    for (int i = 0; i < 32; i += 8)
        T[(size_t)(n0 + ty + i) * K + k0 + tx] = __float2half(t[tx][ty + i]);
}

__global__ void bprep(const float* __restrict__ b, __half* __restrict__ o, int n) {
    int i = blockIdx.x * 256 + threadIdx.x;
    if (i < n) o[i] = __float2half(b[i]);
}

// ---------------------------------------------------------------------------
// LayerNorm -> fp16
// ---------------------------------------------------------------------------
__global__ __launch_bounds__(256) void ln_kernel(
    const float* __restrict__ xin, const float* __restrict__ g,
    const float* __restrict__ b, __half* __restrict__ oh)
{
    __shared__ float red[16];
    const int row = blockIdx.x, tid = threadIdx.x;
    const float* xr = xin + (size_t)row * EMBED;
    const size_t ro = (size_t)row * EMBED;
    float v0 = xr[tid], v1 = xr[tid+256], v2 = xr[tid+512];
    float s = v0+v1+v2, s2 = v0*v0+v1*v1+v2*v2;
    #pragma unroll
    for (int o = 16; o; o >>= 1) {
        s  += __shfl_xor_sync(0xffffffffu, s,  o);
        s2 += __shfl_xor_sync(0xffffffffu, s2, o);
    }
    if ((tid & 31) == 0) { red[tid>>5] = s; red[8+(tid>>5)] = s2; }
    __syncthreads();
    float S=0.f, S2=0.f;
    #pragma unroll
    for (int i = 0; i < 8; i++) { S += red[i]; S2 += red[8+i]; }
    const float mean = S * (1.f/768.f);
    const float rstd = rsqrtf(S2*(1.f/768.f) - mean*mean + 1e-6f);
    oh[ro+tid]     = __float2half((v0-mean)*rstd*g[tid]     + b[tid]);
    oh[ro+tid+256] = __float2half((v1-mean)*rstd*g[tid+256] + b[tid+256]);
    oh[ro+tid+512] = __float2half((v2-mean)*rstd*g[tid+512] + b[tid+512]);
}

// ---------------------------------------------------------------------------
// HMMA GEMM (fp16): C[M,N] = A[M,K] @ B[N,K]^T (+bias).
// CTA 128x128, 8 warps 64x32, K-chunk 64, double-buffered cp.async smem.
// EPI: 0 bias->fp32 | 1 bias+gelu->fp16 | 2 bias+res->fp32 | 3 bias->fp16
// ---------------------------------------------------------------------------
#define LDA        72                      // halves per smem row (64 + 8 pad)
#define TILE_BYTES (128*LDA*2)             // 18432
#define BUF_BYTES  (2*TILE_BYTES)          // A + B = 36864
#define GSM_BYTES  (2*BUF_BYTES)           // 73728

template<int EPI>
__global__ __launch_bounds__(256, 2) void tgemm(
    const __half* __restrict__ A, const __half* __restrict__ B,
    const float* __restrict__ bias, float* __restrict__ Co,
    __half* __restrict__ Ch, int M, int N, int K, const float* __restrict__ res)
{
    extern __shared__ char smc[];
    const uint32_t smb = s2u(smc);
    const int tid = threadIdx.x;
    const int wid = tid >> 5, lane = tid & 31;
    const int bm = blockIdx.y * 128, bn = blockIdx.x * 128;
    const int wm = wid & 1, wn = wid >> 1;
    const int NC = K >> 6;                   // K-chunks of 64

    float acc[4][4][4];
    #pragma unroll
    for (int i = 0; i < 4; i++)
        #pragma unroll
        for (int j = 0; j < 4; j++)
            #pragma unroll
            for (int k = 0; k < 4; k++) acc[i][j][k] = 0.f;

    const uint32_t offA = (uint32_t)((wm*64 + (lane & 7) + 8*((lane >> 3) & 1)) * LDA
                                     + 8*(lane >> 4)) * 2;
    const uint32_t offB = (uint32_t)((wn*32 + (lane & 7) + 8*(lane >> 4)) * LDA
                                     + 8*((lane >> 3) & 1)) * 2;

    auto load_chunk = [&](int c, int b) {
        const int k0 = c << 6;
        const uint32_t bb = smb + b * BUF_BYTES;
        #pragma unroll
        for (int a = 0; a < 2; a++) {
            const __half* G = a ? B : A;
            const int gb = a ? bn : bm;
            const uint32_t ab = bb + a * TILE_BYTES;
            #pragma unroll
            for (int s = 0; s < 4; s++) {
                const int u = tid + s * 256;        // [0,1024)
                const int row = u >> 3, seg = u & 7;
                cp16(ab + (uint32_t)(row * LDA + seg * 8) * 2,
                     G + (size_t)(gb + row) * K + k0 + seg * 8);
            }
        }
        cp_commit();
    };

    load_chunk(0, 0);

    for (int c = 0; c < NC; c++) {
        const int b = c & 1;
        if (c + 1 < NC) {
            load_chunk(c + 1, b ^ 1);
            asm volatile("cp.async.wait_group 1;");
        } else {
            asm volatile("cp.async.wait_group 0;");
        }
        __syncthreads();

        const uint32_t bb = smb + b * BUF_BYTES;
        const uint32_t pA = bb + offA;
        const uint32_t pB = bb + TILE_BYTES + offB;

        #pragma unroll
        for (int ks = 0; ks < 4; ks++) {
            const uint32_t kso = ks * 32;            // 16 halves = 32 bytes
            uint32_t ah[4][4], bh[4][2];
            #pragma unroll
            for (int mt = 0; mt < 4; mt++)
                ldsm_x4(ah[mt][0], ah[mt][1], ah[mt][2], ah[mt][3],
                        pA + kso + mt * (16*LDA*2));
            #pragma unroll
            for (int L = 0; L < 2; L++)
                ldsm_x4(bh[2*L][0], bh[2*L][1], bh[2*L+1][0], bh[2*L+1][1],
                        pB + kso + L * (16*LDA*2));
            #pragma unroll
            for (int mt = 0; mt < 4; mt++)
                #pragma unroll
                for (int nt = 0; nt < 4; nt++)
                    mma16816(acc[mt][nt], ah[mt], bh[nt][0], bh[nt][1]);
        }
        __syncthreads();
    }

    const int rbase = bm + wm*64;
    const int nbase = bn + wn*32;
    #pragma unroll
    for (int mt = 0; mt < 4; mt++) {
        #pragma unroll
        for (int half = 0; half < 2; half++) {
            const int m = rbase + mt*16 + (lane >> 2) + half*8;
            #pragma unroll
            for (int nt = 0; nt < 4; nt++) {
                const int n = nbase + nt*8 + (lane & 3)*2;
                float v0 = acc[mt][nt][half*2 + 0] + bias[n];
                float v1 = acc[mt][nt][half*2 + 1] + bias[n + 1];
                if (EPI == 0) {
                    *(float2*)(Co + (size_t)m * N + n) = make_float2(v0, v1);
                } else if (EPI == 1) {
                    __half2 H;
                    H.x = __float2half(gelu_f(v0));
                    H.y = __float2half(gelu_f(v1));
                    *(__half2*)(Ch + (size_t)m * N + n) = H;
                } else if (EPI == 2) {
                    const float2 r2 = *(const float2*)(res + (size_t)m * N + n);
                    *(float2*)(Co + (size_t)m * N + n) = make_float2(v0 + r2.x, v1 + r2.y);
                } else {
                    __half2 H;
                    H.x = __float2half(v0); H.y = __float2half(v1);
                    *(__half2*)(Ch + (size_t)m * N + n) = H;
                }
            }
        }
    }
}

// ---------------------------------------------------------------------------
// FA2-style window attention on mma.sync. One (window, head) per CTA.
// ---------------------------------------------------------------------------
#define LDH   72           // halves per smem row
#define LDR   72           // rel-pos table row stride (bank-spread)
#define NPAD  208          // tokens padded to 13 x m16
#define OFF_Q 0
#define OFF_K (NPAD*LDH*2)
#define OFF_V (2*NPAD*LDH*2)
#define OFF_RH (3*NPAD*LDH*2)          // 27*LDR halves
#define OFF_RW (OFF_RH + 27*LDR*2)
#define OFF_BH (OFF_RW + 27*LDR*2)     // 196*14 halves
#define OFF_BW (OFF_BH + 196*14*2)
#define ATTN_SMEM (OFF_BW + 196*14*2)  // 108608 B

__global__ __launch_bounds__(256, 2) void attn_kernel(
    const __half* __restrict__ qkv, const __half* __restrict__ bq16,
    const float* __restrict__ relh, const float* __restrict__ relw,
    __half* __restrict__ ao)
{
    extern __shared__ char smc[];
    const uint32_t smb = s2u(smc);
    __half* Qh = (__half*)(smc + OFF_Q);
    __half* Kh = (__half*)(smc + OFF_K);
    __half* Vh = (__half*)(smc + OFF_V);
    __half* Rh = (__half*)(smc + OFF_RH);
    __half* Rw = (__half*)(smc + OFF_RW);
    __half* BH = (__half*)(smc + OFF_BH);
    __half* BW = (__half*)(smc + OFF_BW);

    const int tid = threadIdx.x;
    const int w = blockIdx.x / NHEAD, h = blockIdx.x % NHEAD;
    const int bI = w / 25, wr = w % 25;
    const int wy = wr / 5, wx = wr % 5;
    const int wid = tid >> 5, lane = tid & 31;

    // ---- load Q,K,V (fp16) with window gather; pad rows with zeros ----
    for (int idx = tid; idx < NTOK * 8; idx += 256) {
        const int t = idx >> 3, seg = idx & 7;
        const int y = wy * 14 + t / 14, xx = wx * 14 + t % 14;
        const __half* rp = (y < 64 && xx < 64)
            ? qkv + (size_t)((bI * 64 + y) * 64 + xx) * QKVN + h * HD + seg * 8
            : bq16 + h * HD + seg * 8;
        *(uint4*)&Qh[t * LDH + seg * 8] = *(const uint4*)(rp);
        *(uint4*)&Kh[t * LDH + seg * 8] = *(const uint4*)(rp + 768);
        *(uint4*)&Vh[t * LDH + seg * 8] = *(const uint4*)(rp + 1536);
    }
    for (int idx = tid; idx < (NPAD - NTOK) * 8; idx += 256) {
        const int t = NTOK + (idx >> 3), seg = idx & 7;
        const uint4 z = make_uint4(0, 0, 0, 0);
        *(uint4*)&Qh[t * LDH + seg * 8] = z;
        *(uint4*)&Kh[t * LDH + seg * 8] = z;
        *(uint4*)&Vh[t * LDH + seg * 8] = z;
    }
    for (int idx = tid; idx < 27 * 64; idx += 256) {
        const int rr = idx >> 6, cc = idx & 63;
        Rh[rr * LDR + cc] = __float2half(relh[idx]);
        Rw[rr * LDR + cc] = __float2half(relw[idx]);
    }
    __syncthreads();

    // ---- rel-pos bias tables: lane L owns (r = L>>1, d-half = L&1) ----
    for (int i = wid; i < NTOK; i += 8) {
        const int p = i / 14, qc = i % 14;
        if (lane < 28) {
            const int r = lane >> 1, hf = lane & 1;
            const __half* qrow  = &Qh[i * LDH + hf * 32];
            const __half* rhrow = &Rh[(p  + 13 - r) * LDR + hf * 32];
            const __half* rwrow = &Rw[(qc + 13 - r) * LDR + hf * 32];
            float ah = 0.f, aw = 0.f;
            #pragma unroll
            for (int k = 0; k < 16; k++) {
                const float2 q2 = __half22float2(*(const __half2*)(qrow + 2*k));
                const float2 h2 = __half22float2(*(const __half2*)(rhrow + 2*k));
                const float2 w2 = __half22float2(*(const __half2*)(rwrow + 2*k));
                ah += q2.x * h2.x + q2.y * h2.y;
                aw += q2.x * w2.x + q2.y * w2.y;
            }
            ah += __shfl_xor_sync(0x0fffffffu, ah, 1);
            aw += __shfl_xor_sync(0x0fffffffu, aw, 1);
            if (hf == 0) {
                BH[i*14 + r] = __float2half(ah);
                BW[i*14 + r] = __float2half(aw);
            }
        }
    }
    __syncthreads();

    const float SCALE = 0.125f;
    const uint32_t qb = smb + OFF_Q, kb = smb + OFF_K, vb = smb + OFF_V;

    // ---- per m16 tile: online-softmax FA loop over 13 key chunks of 16 ----
    for (int tile = wid; tile < 13; tile += 8) {
        uint32_t aq[4][4];
        #pragma unroll
        for (int kk = 0; kk < 4; kk++)
            ldsm_x4(aq[kk][0], aq[kk][1], aq[kk][2], aq[kk][3],
                    qb + (uint32_t)((tile*16 + (lane&7) + 8*((lane>>3)&1)) * LDH
                                    + kk*16 + 8*(lane>>4)) * 2);

        float o[8][4];
        #pragma unroll
        for (int i = 0; i < 8; i++)
            #pragma unroll
            for (int j = 0; j < 4; j++) o[i][j] = 0.f;
        float mrun0 = -1e30f, mrun1 = -1e30f, lrun0 = 0.f, lrun1 = 0.f;

        const int i0 = tile*16 + (lane >> 2);
        const int i0c = (i0 < NTOK ? i0 : 0), i1c = (i0 + 8 < NTOK ? i0 + 8 : 0);

        for (int kc = 0; kc < 13; kc++) {
            float S0[4], S1[4];
            #pragma unroll
            for (int j = 0; j < 4; j++) { S0[j] = 0.f; S1[j] = 0.f; }
            #pragma unroll
            for (int kk = 0; kk < 4; kk++) {
                uint32_t r0, r1, r2, r3;
                ldsm_x4(r0, r1, r2, r3,
                        kb + (uint32_t)((kc*16 + (lane&7) + 8*(lane>>4)) * LDH
                                        + kk*16 + 8*((lane>>3)&1)) * 2);
                mma16816(S0, aq[kk], r0, r1);
                mma16816(S1, aq[kk], r2, r3);
            }
            const int j0 = kc*16 + 2*(lane & 3);
            float s[2][4];
            #pragma unroll
            for (int e = 0; e < 4; e++) {
                const int j = j0 + (e & 1) + (e >> 1) * 8;
                bool ok = (j < NTOK);
                int jp = 0, jq = 0;
                if (ok) { jp = j / 14; jq = j - jp * 14; }
                const float b0 = __half2float(BH[i0c*14+jp]) + __half2float(BW[i0c*14+jq]);
                const float b1 = __half2float(BH[i1c*14+jp]) + __half2float(BW[i1c*14+jq]);
                const float r0v = (e >> 1) ? S1[e & 1] : S0[e & 1];
                const float r1v = (e >> 1) ? S1[2 + (e & 1)] : S0[2 + (e & 1)];
                s[0][e] = ok ? r0v * SCALE + b0 : -1e30f;
                s[1][e] = ok ? r1v * SCALE + b1 : -1e30f;
            }
            float mx0 = fmaxf(fmaxf(s[0][0], s[0][1]), fmaxf(s[0][2], s[0][3]));
            float mx1 = fmaxf(fmaxf(s[1][0], s[1][1]), fmaxf(s[1][2], s[1][3]));
            mx0 = fmaxf(mx0, __shfl_xor_sync(0xffffffffu, mx0, 1));
            mx0 = fmaxf(mx0, __shfl_xor_sync(0xffffffffu, mx0, 2));
            mx1 = fmaxf(mx1, __shfl_xor_sync(0xffffffffu, mx1, 1));
            mx1 = fmaxf(mx1, __shfl_xor_sync(0xffffffffu, mx1, 2));
            const float mn0 = fmaxf(mrun0, mx0), mn1 = fmaxf(mrun1, mx1);
            float sc0 = 1.f, sc1 = 1.f;
            const bool nochange = (mn0 == mrun0) && (mn1 == mrun1);
            if (!__all_sync(0xffffffffu, nochange)) {
                sc0 = __expf(mrun0 - mn0);
                sc1 = __expf(mrun1 - mn1);
                #pragma unroll
                for (int dt = 0; dt < 8; dt++) {
                    o[dt][0] *= sc0; o[dt][1] *= sc0;
                    o[dt][2] *= sc1; o[dt][3] *= sc1;
                }
            }
            mrun0 = mn0; mrun1 = mn1;
            float p[2][4], rs0 = 0.f, rs1 = 0.f;
            #pragma unroll
            for (int e = 0; e < 4; e++) {
                p[0][e] = __expf(s[0][e] - mn0);
                p[1][e] = __expf(s[1][e] - mn1);
                rs0 += p[0][e]; rs1 += p[1][e];
            }
            rs0 += __shfl_xor_sync(0xffffffffu, rs0, 1);
            rs0 += __shfl_xor_sync(0xffffffffu, rs0, 2);
            rs1 += __shfl_xor_sync(0xffffffffu, rs1, 1);
            rs1 += __shfl_xor_sync(0xffffffffu, rs1, 2);
            lrun0 = lrun0 * sc0 + rs0;
            lrun1 = lrun1 * sc1 + rs1;
            uint32_t ap[4];
            ap[0] = packh2(p[0][0], p[0][1]);
            ap[1] = packh2(p[1][0], p[1][1]);
            ap[2] = packh2(p[0][2], p[0][3]);
            ap[3] = packh2(p[1][2], p[1][3]);
            #pragma unroll
            for (int nn = 0; nn < 4; nn++) {
                uint32_t r0, r1, r2, r3;
                ldsm_x4t(r0, r1, r2, r3,
                         vb + (uint32_t)((kc*16 + (lane & 15)) * LDH
                                         + nn*16 + 8*(lane>>4)) * 2);
                mma16816(o[2*nn],     ap, r0, r1);
                mma16816(o[2*nn + 1], ap, r2, r3);
            }
        }

        // ---- write out (scatter to compact layout) ----
        const float inv0 = 1.f / lrun0, inv1 = 1.f / lrun1;
        #pragma unroll
        for (int half = 0; half < 2; half++) {
            const int i = tile*16 + (lane >> 2) + half*8;
            if (i >= NTOK) continue;
            const int y = wy*14 + i/14, xx = wx*14 + i%14;
            if (y >= 64 || xx >= 64) continue;
            __half* orow = ao + (size_t)((bI*64 + y)*64 + xx) * EMBED + h * HD;
            const float inv = half ? inv1 : inv0;
            #pragma unroll
            for (int dt = 0; dt < 8; dt++) {
                __half2 H;
                H.x = __float2half(o[dt][half*2 + 0] * inv);
                H.y = __float2half(o[dt][half*2 + 1] * inv);
                *(__half2*)(orow + dt*8 + 2*(lane & 3)) = H;
            }
        }
    }
}

// ---------------------------------------------------------------------------
// kernel_launch
// ---------------------------------------------------------------------------
extern "C" void kernel_launch(void* const* d_in, const int* in_sizes, int n_in,
                              void* d_out, int out_size)
{
    const float* x      = (const float*)d_in[0];
    const float* g1     = (const float*)d_in[1];
    const float* beta1  = (const float*)d_in[2];
    const float* w_qkv  = (const float*)d_in[3];
    const float* b_qkv  = (const float*)d_in[4];
    const float* w_proj = (const float*)d_in[5];
    const float* b_proj = (const float*)d_in[6];
    const float* relh   = (const float*)d_in[7];
    const float* relw   = (const float*)d_in[8];
    const float* g2     = (const float*)d_in[9];
    const float* beta2  = (const float*)d_in[10];
    const float* w_fc1  = (const float*)d_in[11];
    const float* b_fc1  = (const float*)d_in[12];
    const float* w_fc2  = (const float*)d_in[13];
    const float* b_fc2  = (const float*)d_in[14];
    float* out = (float*)d_out;

    __half *hwin, *qkv, *attn, *h2, *ff, *bq16, *wqkv, *wprj, *wf1, *wf2;
    float *x1;
    cudaGetSymbolAddress((void**)&hwin, g_hwin);
    cudaGetSymbolAddress((void**)&qkv,  g_qkv);
    cudaGetSymbolAddress((void**)&attn, g_attn);
    cudaGetSymbolAddress((void**)&x1,   g_x1);
    cudaGetSymbolAddress((void**)&h2,   g_h2);
    cudaGetSymbolAddress((void**)&ff,   g_ff);
    cudaGetSymbolAddress((void**)&bq16, g_bq16);
    cudaGetSymbolAddress((void**)&wqkv, g_wqkv);
    cudaGetSymbolAddress((void**)&wprj, g_wprj);
    cudaGetSymbolAddress((void**)&wf1,  g_wfc1);
    cudaGetSymbolAddress((void**)&wf2,  g_wfc2);

    cudaFuncSetAttribute(attn_kernel, cudaFuncAttributeMaxDynamicSharedMemorySize, ATTN_SMEM);
    cudaFuncSetAttribute(tgemm<1>, cudaFuncAttributeMaxDynamicSharedMemorySize, GSM_BYTES);
    cudaFuncSetAttribute(tgemm<2>, cudaFuncAttributeMaxDynamicSharedMemorySize, GSM_BYTES);
    cudaFuncSetAttribute(tgemm<3>, cudaFuncAttributeMaxDynamicSharedMemorySize, GSM_BYTES);

    // [0] LN1
    ln_kernel<<<M_TOK, 256>>>(x, g1, beta1, hwin);

    // [1-4] weight prep
    wprep<<<dim3(QKVN/32, EMBED/32), 256>>>(w_qkv,  wqkv, EMBED, QKVN);
    wprep<<<dim3(EMBED/32, EMBED/32), 256>>>(w_proj, wprj, EMBED, EMBED);
    wprep<<<dim3(FFDIM/32, EMBED/32), 256>>>(w_fc1,  wf1,  EMBED, FFDIM);
    wprep<<<dim3(EMBED/32, FFDIM/32), 256>>>(w_fc2,  wf2,  FFDIM, EMBED);

    // [5] QKV projection -> fp16 (ncu capture target)
    tgemm<3><<<dim3(QKVN/128, M_TOK/128), 256, GSM_BYTES>>>(
        hwin, wqkv, b_qkv, nullptr, qkv, M_TOK, QKVN, EMBED, nullptr);

    // [6] bias -> fp16
    bprep<<<(QKVN + 255)/256, 256>>>(b_qkv, bq16, QKVN);

    // [7] window attention (tensor-core FA)
    attn_kernel<<<NWIN * NHEAD, 256, ATTN_SMEM>>>(qkv, bq16, relh, relw, attn);

    // [8] proj + residual: x1 = x + attn @ w_proj + b_proj
    tgemm<2><<<dim3(EMBED/128, M_TOK/128), 256, GSM_BYTES>>>(
        attn, wprj, b_proj, x1, nullptr, M_TOK, EMBED, EMBED, x);

    // [9] LN2
    ln_kernel<<<M_TOK, 256>>>(x1, g2, beta2, h2);

    // [10] fc1 + GELU -> fp16
    tgemm<1><<<dim3(FFDIM/128, M_TOK/128), 256, GSM_BYTES>>>(
        h2, wf1, b_fc1, nullptr, ff, M_TOK, FFDIM, EMBED, nullptr);

    // [11] fc2 + residual -> out
    tgemm<2><<<dim3(EMBED/128, M_TOK/128), 256, GSM_BYTES>>>(
        ff, wf2, b_fc2, out, nullptr, M_TOK, EMBED, FFDIM, x1);
}